// round 2
// baseline (speedup 1.0000x reference)
#include <cuda_runtime.h>
#include <math.h>

#define B_ 8
#define N_ 512
#define D_ 512
#define H_ 8
#define DK_ 64
#define BNT 4096                 // B*N
#define NN_ 262144               // N*N

// ---------------- scratch (static device globals; no allocation allowed) ----
__device__ float g_q [BNT * D_];
__device__ float g_k [BNT * D_];
__device__ float g_v [BNT * D_];
__device__ float g_ao[BNT * D_];
__device__ float g_S [(long long)B_ * H_ * NN_];   // scores, then probs (in place)
__device__ float g_F [(long long)B_ * H_ * NN_];   // geometry factor gfac
__device__ float g_cx[BNT], g_cy[BNT], g_lw[BNT], g_lh[BNT], g_iw[BNT], g_ih[BNT], g_no[BNT];
__device__ int   g_isbyte;

// 100 / 1000^(m/8)
__constant__ float c_DM[8] = {
    100.0f, 42.169650342858224f, 17.78279410038923f, 7.498942093324559f,
    3.1622776601683795f, 1.3335214321633242f, 0.5623413251903491f, 0.23713737056616555f};

// ---------------- detect layout of not_objects (bool-as-int32 vs bytes) ----
// Reads first 1024 int32 words (4KB: in-bounds under either layout). If any
// word is outside {0,1}, the buffer must be byte-packed bools.
__global__ void detect_nobj(const int* __restrict__ p) {
    __shared__ int bad[256];
    int t = threadIdx.x;
    int v = 0;
    for (int i = t; i < 1024; i += 256) {
        int x = p[i];
        v |= (x != 0 && x != 1);
    }
    bad[t] = v;
    __syncthreads();
    for (int s = 128; s; s >>= 1) {
        if (t < s) bad[t] |= bad[t + s];
        __syncthreads();
    }
    if (t == 0) g_isbyte = bad[0];
}

// ---------------- per-box precompute ---------------------------------------
__global__ void box_pre(const float* __restrict__ box, const void* __restrict__ nobj) {
    int i = blockIdx.x * blockDim.x + threadIdx.x;
    if (i >= BNT) return;
    float x0 = box[4*i+0], y0 = box[4*i+1], x1 = box[4*i+2], y1 = box[4*i+3];
    float w = x1 - x0 + 1.0f, h = y1 - y0 + 1.0f;
    g_cx[i] = 0.5f * (x0 + x1);
    g_cy[i] = 0.5f * (y0 + y1);
    g_lw[i] = logf(w);
    g_lh[i] = logf(h);
    g_iw[i] = 1.0f / w;
    g_ih[i] = 1.0f / h;
    int nv = g_isbyte ? (int)((const unsigned char*)nobj)[i]
                      : ((const int*)nobj)[i];
    g_no[i] = nv ? 1.0f : 0.0f;
}

// Cody-Waite reduced fast sincos: accurate for |x| up to ~800 (k < 128).
__device__ __forceinline__ void fsincos(float x, float& s, float& c) {
    float k = rintf(x * 0.15915494309189535f);
    float r = __fmaf_rn(k, -6.28125f, x);                 // coarse 2*pi chunk: k*c1 exact
    r = __fmaf_rn(k, -1.9353071795864769e-3f, r);         // 2*pi - 6.28125
    s = __sinf(r);
    c = __cosf(r);
}

// ---------------- geometry factor: gfac[b,h,i,j] ---------------------------
// gfac = mask_obj ? clip(relu(z), 1e-6) : 1.0, where
// z = sum_g sin/cos(100*pos*dm) * WG + bG.  (log is folded into softmax.)
__global__ void __launch_bounds__(128) geom_kernel(const float* __restrict__ WG,
                                                   const float* __restrict__ bG) {
    __shared__ float sWs[32][8];   // WG[h][g]   (sin part), stored [g][h]
    __shared__ float sWc[32][8];   // WG[h][32+g](cos part)
    __shared__ float sbG[8];
    int t = threadIdx.x;
    for (int x = t; x < 512; x += 128) {
        int h = x >> 6, g = x & 63;
        if (g < 32) sWs[g][h] = WG[x];
        else        sWc[g - 32][h] = WG[x];
    }
    if (t < 8) sbG[t] = bG[t];
    __syncthreads();

    int row = blockIdx.x;
    int b = row >> 9, i = row & 511;
    int base = b << 9;
    float cxi = g_cx[base + i], cyi = g_cy[base + i];
    float iwi = g_iw[base + i], ihi = g_ih[base + i];
    float lwi = g_lw[base + i], lhi = g_lh[base + i];
    float noi = g_no[base + i];

    for (int j = t; j < N_; j += 128) {
        int jj = base + j;
        float dx = __logf(fmaxf(fabsf(g_cx[jj] - cxi) * iwi, 1e-3f));
        float dy = __logf(fmaxf(fabsf(g_cy[jj] - cyi) * ihi, 1e-3f));
        float dw = lwi - g_lw[jj];
        float dh = lhi - g_lh[jj];
        float pos[4] = {dx, dy, dw, dh};

        float acc[8];
        #pragma unroll
        for (int h = 0; h < 8; h++) acc[h] = sbG[h];

        #pragma unroll
        for (int kk = 0; kk < 4; kk++) {
            #pragma unroll
            for (int m = 0; m < 8; m++) {
                float s, c;
                fsincos(pos[kk] * c_DM[m], s, c);
                int g = kk * 8 + m;
                float4 ws0 = *(const float4*)&sWs[g][0];
                float4 ws1 = *(const float4*)&sWs[g][4];
                float4 wc0 = *(const float4*)&sWc[g][0];
                float4 wc1 = *(const float4*)&sWc[g][4];
                acc[0] = fmaf(s, ws0.x, fmaf(c, wc0.x, acc[0]));
                acc[1] = fmaf(s, ws0.y, fmaf(c, wc0.y, acc[1]));
                acc[2] = fmaf(s, ws0.z, fmaf(c, wc0.z, acc[2]));
                acc[3] = fmaf(s, ws0.w, fmaf(c, wc0.w, acc[3]));
                acc[4] = fmaf(s, ws1.x, fmaf(c, wc1.x, acc[4]));
                acc[5] = fmaf(s, ws1.y, fmaf(c, wc1.y, acc[5]));
                acc[6] = fmaf(s, ws1.z, fmaf(c, wc1.z, acc[6]));
                acc[7] = fmaf(s, ws1.w, fmaf(c, wc1.w, acc[7]));
            }
        }
        bool obj = (fmaxf(noi, g_no[jj]) < 0.5f);
        long long o = (long long)b * H_ * NN_ + (long long)i * N_ + j;
        #pragma unroll
        for (int h = 0; h < 8; h++) {
            float gf = obj ? fmaxf(acc[h], 1e-6f) : 1.0f;
            g_F[o + (long long)h * NN_] = gf;
        }
    }
}

// ---------------- generic batched SGEMM (64x64x16 tiles, 256 thr, 4x4/thr) -
// mode 0: C = A*B*alpha + bias      (bias per column)
// mode 1: C = A*B*alpha, then C = -1e9 where mask[col]==0   (scores)
// mode 2: C = A*B*alpha
// transB: B accessed as B[n*ldb + k] (i.e. C = A * B^T)
#define BM 64
#define BN 64
#define BK 16
__global__ void __launch_bounds__(256) sgemm(
    const float* __restrict__ A, const float* __restrict__ B, float* __restrict__ C,
    int M, int N, int K, int lda, int ldb, int ldc,
    long long sAb, long long sAh, long long sBb, long long sBh, long long sCb, long long sCh,
    float alpha, const float* __restrict__ bias, const int* __restrict__ mask,
    int transB, int mode, int Hdiv)
{
    int z = blockIdx.z;
    int bb = z / Hdiv, hh = z - bb * Hdiv;
    A += (long long)bb * sAb + (long long)hh * sAh;
    B += (long long)bb * sBb + (long long)hh * sBh;
    C += (long long)bb * sCb + (long long)hh * sCh;
    const int* mrow = mask ? (mask + (long long)bb * N_) : nullptr;

    __shared__ float As[BK][BM];
    __shared__ float Bs[BK][BN];
    int t = threadIdx.x;
    int m0 = blockIdx.y * BM, n0 = blockIdx.x * BN;
    int ty = t >> 4, tx = t & 15;
    float acc[4][4];
    #pragma unroll
    for (int a = 0; a < 4; a++)
        #pragma unroll
        for (int b2 = 0; b2 < 4; b2++) acc[a][b2] = 0.0f;

    int am = t >> 2, ak = (t & 3) << 2;

    for (int k0 = 0; k0 < K; k0 += BK) {
        float4 a4 = *(const float4*)(A + (long long)(m0 + am) * lda + k0 + ak);
        As[ak + 0][am] = a4.x; As[ak + 1][am] = a4.y;
        As[ak + 2][am] = a4.z; As[ak + 3][am] = a4.w;
        if (!transB) {
            int bk = t >> 4, bn = (t & 15) << 2;
            *(float4*)&Bs[bk][bn] = *(const float4*)(B + (long long)(k0 + bk) * ldb + n0 + bn);
        } else {
            int bn = t >> 2, bk = (t & 3) << 2;
            float4 b4 = *(const float4*)(B + (long long)(n0 + bn) * ldb + k0 + bk);
            Bs[bk + 0][bn] = b4.x; Bs[bk + 1][bn] = b4.y;
            Bs[bk + 2][bn] = b4.z; Bs[bk + 3][bn] = b4.w;
        }
        __syncthreads();
        #pragma unroll
        for (int k = 0; k < BK; k++) {
            float4 av = *(const float4*)&As[k][ty << 2];
            float4 bv = *(const float4*)&Bs[k][tx << 2];
            float ar[4] = {av.x, av.y, av.z, av.w};
            float br[4] = {bv.x, bv.y, bv.z, bv.w};
            #pragma unroll
            for (int ii = 0; ii < 4; ii++)
                #pragma unroll
                for (int jj = 0; jj < 4; jj++)
                    acc[ii][jj] = fmaf(ar[ii], br[jj], acc[ii][jj]);
        }
        __syncthreads();
    }

    int cbase = n0 + (tx << 2);
    #pragma unroll
    for (int ii = 0; ii < 4; ii++) {
        int r = m0 + (ty << 2) + ii;
        float vv[4];
        #pragma unroll
        for (int jj = 0; jj < 4; jj++) {
            float v = acc[ii][jj] * alpha;
            int col = cbase + jj;
            if (mode == 0)      v += bias[col];
            else if (mode == 1) { if (mrow[col] == 0) v = -1e9f; }
            vv[jj] = v;
        }
        *(float4*)(C + (long long)r * ldc + cbase) = make_float4(vv[0], vv[1], vv[2], vv[3]);
    }
}

// ---------------- fused softmax: p = gfac * exp(s - max) / sum -------------
__global__ void __launch_bounds__(128) softmax_k() {
    long long off = (long long)blockIdx.x * N_;
    float* S = g_S + off;
    const float* F = g_F + off;
    int t = threadIdx.x;
    float s0 = S[t], s1 = S[t + 128], s2 = S[t + 256], s3 = S[t + 384];
    float mx = fmaxf(fmaxf(s0, s1), fmaxf(s2, s3));
    __shared__ float sh[4], sh2[4];
    #pragma unroll
    for (int o = 16; o; o >>= 1) mx = fmaxf(mx, __shfl_xor_sync(0xffffffffu, mx, o));
    if ((t & 31) == 0) sh[t >> 5] = mx;
    __syncthreads();
    mx = fmaxf(fmaxf(sh[0], sh[1]), fmaxf(sh[2], sh[3]));
    float p0 = F[t]       * __expf(s0 - mx);
    float p1 = F[t + 128] * __expf(s1 - mx);
    float p2 = F[t + 256] * __expf(s2 - mx);
    float p3 = F[t + 384] * __expf(s3 - mx);
    float sum = p0 + p1 + p2 + p3;
    #pragma unroll
    for (int o = 16; o; o >>= 1) sum += __shfl_xor_sync(0xffffffffu, sum, o);
    if ((t & 31) == 0) sh2[t >> 5] = sum;
    __syncthreads();
    sum = sh2[0] + sh2[1] + sh2[2] + sh2[3];
    float inv = 1.0f / sum;
    S[t] = p0 * inv; S[t + 128] = p1 * inv; S[t + 256] = p2 * inv; S[t + 384] = p3 * inv;
}

// ---------------- launch ----------------------------------------------------
extern "C" void kernel_launch(void* const* d_in, const int* in_sizes, int n_in,
                              void* d_out, int out_size) {
    const float* inq = (const float*)d_in[0];
    const float* ink = (const float*)d_in[1];
    const float* inv = (const float*)d_in[2];
    const float* box = (const float*)d_in[3];
    const int*   msk = (const int*)d_in[4];
    const void*  nob = d_in[5];
    const float* Wq = (const float*)d_in[6];  const float* bq = (const float*)d_in[7];
    const float* Wk = (const float*)d_in[8];  const float* bk = (const float*)d_in[9];
    const float* Wv = (const float*)d_in[10]; const float* bv = (const float*)d_in[11];
    const float* Wo = (const float*)d_in[12]; const float* bo = (const float*)d_in[13];
    const float* WG = (const float*)d_in[14]; const float* bG = (const float*)d_in[15];
    float* out = (float*)d_out;

    float *pq, *pk, *pv, *pao, *pS;
    cudaGetSymbolAddress((void**)&pq,  g_q);
    cudaGetSymbolAddress((void**)&pk,  g_k);
    cudaGetSymbolAddress((void**)&pv,  g_v);
    cudaGetSymbolAddress((void**)&pao, g_ao);
    cudaGetSymbolAddress((void**)&pS,  g_S);

    detect_nobj<<<1, 256>>>((const int*)nob);
    box_pre<<<32, 128>>>(box, nob);
    geom_kernel<<<BNT, 128>>>(WG, bG);

    dim3 gP(8, 64, 1);   // 4096x512x512
    sgemm<<<gP, 256>>>(inq, Wq, pq, BNT, D_, D_, D_, D_, D_,
                       0, 0, 0, 0, 0, 0, 1.0f, bq, nullptr, 0, 0, 1);
    sgemm<<<gP, 256>>>(ink, Wk, pk, BNT, D_, D_, D_, D_, D_,
                       0, 0, 0, 0, 0, 0, 1.0f, bk, nullptr, 0, 0, 1);
    sgemm<<<gP, 256>>>(inv, Wv, pv, BNT, D_, D_, D_, D_, D_,
                       0, 0, 0, 0, 0, 0, 1.0f, bv, nullptr, 0, 0, 1);

    // scores: S[b,h,i,j] = 0.125 * q_i . k_j, masked to -1e9 on mask[b,j]==0
    dim3 gS(8, 8, 64);
    sgemm<<<gS, 256>>>(pq, pk, pS, N_, N_, DK_, D_, D_, N_,
                       (long long)N_ * D_, 64, (long long)N_ * D_, 64,
                       (long long)H_ * NN_, (long long)NN_,
                       0.125f, nullptr, msk, 1, 1, H_);

    softmax_k<<<B_ * H_ * N_, 128>>>();

    // O = P * V
    dim3 gA(1, 8, 64);
    sgemm<<<gA, 256>>>(pS, pv, pao, N_, DK_, N_, N_, D_, D_,
                       (long long)H_ * NN_, (long long)NN_,
                       (long long)N_ * D_, 64, (long long)N_ * D_, 64,
                       1.0f, nullptr, nullptr, 0, 2, H_);

    sgemm<<<gP, 256>>>(pao, Wo, out, BNT, D_, D_, D_, D_, D_,
                       0, 0, 0, 0, 0, 0, 1.0f, bo, nullptr, 0, 0, 1);
}

// round 3
// speedup vs baseline: 1.0867x; 1.0867x over previous
#include <cuda_runtime.h>
#include <math.h>

#define B_ 8
#define N_ 512
#define D_ 512
#define H_ 8
#define DK_ 64
#define BNT 4096                 // B*N
#define NN_ 262144               // N*N

// ---------------- scratch (static device globals; no allocation allowed) ----
__device__ float g_q [BNT * D_];
__device__ float g_k [BNT * D_];
__device__ float g_v [BNT * D_];
__device__ float g_ao[BNT * D_];
__device__ float g_F [(long long)B_ * H_ * NN_];   // geometry factor gfac
__device__ float g_cx[BNT], g_cy[BNT], g_lw[BNT], g_lh[BNT], g_iw[BNT], g_ih[BNT], g_no[BNT];
__device__ int   g_isbyte;

// 100 / 1000^(m/8)
__constant__ float c_DM[8] = {
    100.0f, 42.169650342858224f, 17.78279410038923f, 7.498942093324559f,
    3.1622776601683795f, 1.3335214321633242f, 0.5623413251903491f, 0.23713737056616555f};

// ---------------- detect layout of not_objects (bool-as-int32 vs bytes) ----
__global__ void detect_nobj(const int* __restrict__ p) {
    __shared__ int bad[256];
    int t = threadIdx.x;
    int v = 0;
    for (int i = t; i < 1024; i += 256) {
        int x = p[i];
        v |= (x != 0 && x != 1);
    }
    bad[t] = v;
    __syncthreads();
    for (int s = 128; s; s >>= 1) {
        if (t < s) bad[t] |= bad[t + s];
        __syncthreads();
    }
    if (t == 0) g_isbyte = bad[0];
}

// ---------------- per-box precompute ---------------------------------------
__global__ void box_pre(const float* __restrict__ box, const void* __restrict__ nobj) {
    int i = blockIdx.x * blockDim.x + threadIdx.x;
    if (i >= BNT) return;
    float x0 = box[4*i+0], y0 = box[4*i+1], x1 = box[4*i+2], y1 = box[4*i+3];
    float w = x1 - x0 + 1.0f, h = y1 - y0 + 1.0f;
    g_cx[i] = 0.5f * (x0 + x1);
    g_cy[i] = 0.5f * (y0 + y1);
    g_lw[i] = logf(w);
    g_lh[i] = logf(h);
    g_iw[i] = 1.0f / w;
    g_ih[i] = 1.0f / h;
    int nv = g_isbyte ? (int)((const unsigned char*)nobj)[i]
                      : ((const int*)nobj)[i];
    g_no[i] = nv ? 1.0f : 0.0f;
}

// Cody-Waite reduced fast sincos: accurate for |x| up to ~800.
__device__ __forceinline__ void fsincos(float x, float& s, float& c) {
    float k = rintf(x * 0.15915494309189535f);
    float r = __fmaf_rn(k, -6.28125f, x);
    r = __fmaf_rn(k, -1.9353071795864769e-3f, r);
    s = __sinf(r);
    c = __cosf(r);
}

// ---------------- geometry factor: gfac[b,h,i,j] ---------------------------
__global__ void __launch_bounds__(128) geom_kernel(const float* __restrict__ WG,
                                                   const float* __restrict__ bG) {
    __shared__ float sWs[32][8];
    __shared__ float sWc[32][8];
    __shared__ float sbG[8];
    int t = threadIdx.x;
    for (int x = t; x < 512; x += 128) {
        int h = x >> 6, g = x & 63;
        if (g < 32) sWs[g][h] = WG[x];
        else        sWc[g - 32][h] = WG[x];
    }
    if (t < 8) sbG[t] = bG[t];
    __syncthreads();

    int row = blockIdx.x;
    int b = row >> 9, i = row & 511;
    int base = b << 9;
    float cxi = g_cx[base + i], cyi = g_cy[base + i];
    float iwi = g_iw[base + i], ihi = g_ih[base + i];
    float lwi = g_lw[base + i], lhi = g_lh[base + i];
    float noi = g_no[base + i];

    for (int j = t; j < N_; j += 128) {
        int jj = base + j;
        float dx = __logf(fmaxf(fabsf(g_cx[jj] - cxi) * iwi, 1e-3f));
        float dy = __logf(fmaxf(fabsf(g_cy[jj] - cyi) * ihi, 1e-3f));
        float dw = lwi - g_lw[jj];
        float dh = lhi - g_lh[jj];
        float pos[4] = {dx, dy, dw, dh};

        float acc[8];
        #pragma unroll
        for (int h = 0; h < 8; h++) acc[h] = sbG[h];

        #pragma unroll
        for (int kk = 0; kk < 4; kk++) {
            #pragma unroll
            for (int m = 0; m < 8; m++) {
                float s, c;
                fsincos(pos[kk] * c_DM[m], s, c);
                int g = kk * 8 + m;
                float4 ws0 = *(const float4*)&sWs[g][0];
                float4 ws1 = *(const float4*)&sWs[g][4];
                float4 wc0 = *(const float4*)&sWc[g][0];
                float4 wc1 = *(const float4*)&sWc[g][4];
                acc[0] = fmaf(s, ws0.x, fmaf(c, wc0.x, acc[0]));
                acc[1] = fmaf(s, ws0.y, fmaf(c, wc0.y, acc[1]));
                acc[2] = fmaf(s, ws0.z, fmaf(c, wc0.z, acc[2]));
                acc[3] = fmaf(s, ws0.w, fmaf(c, wc0.w, acc[3]));
                acc[4] = fmaf(s, ws1.x, fmaf(c, wc1.x, acc[4]));
                acc[5] = fmaf(s, ws1.y, fmaf(c, wc1.y, acc[5]));
                acc[6] = fmaf(s, ws1.z, fmaf(c, wc1.z, acc[6]));
                acc[7] = fmaf(s, ws1.w, fmaf(c, wc1.w, acc[7]));
            }
        }
        bool obj = (fmaxf(noi, g_no[jj]) < 0.5f);
        long long o = (long long)b * H_ * NN_ + (long long)i * N_ + j;
        #pragma unroll
        for (int h = 0; h < 8; h++) {
            float gf = obj ? fmaxf(acc[h], 1e-6f) : 1.0f;
            g_F[o + (long long)h * NN_] = gf;
        }
    }
}

// ---------------- projection GEMM: C[4096,512] = A @ W + bias --------------
// 128x128x16 tiles, 256 threads, 8x8 per thread (quad layout), double-buffered.
__global__ void __launch_bounds__(256) proj_gemm(
    const float* __restrict__ A, const float* __restrict__ W,
    const float* __restrict__ bias, float* __restrict__ C)
{
    __shared__ float As[2][16][128];
    __shared__ float Bs[2][16][128];
    int t = threadIdx.x;
    int ty4 = (t >> 4) << 2, tx4 = (t & 15) << 2;
    int m0 = blockIdx.y << 7, n0 = blockIdx.x << 7;
    int am = t & 127, ak = (t >> 7) << 2;          // ak in {0,4}
    int bk = t >> 5,  bn = (t & 31) << 2;          // bk 0..7
    const float* Ap = A + (long long)(m0 + am) * D_;
    const float* Wp = W + n0;

    float acc[8][8];
    #pragma unroll
    for (int i = 0; i < 8; i++)
        #pragma unroll
        for (int j = 0; j < 8; j++) acc[i][j] = 0.0f;

    float4 a0 = *(const float4*)(Ap + ak);
    float4 a1 = *(const float4*)(Ap + ak + 8);
    float4 b0 = *(const float4*)(Wp + (long long)bk * D_ + bn);
    float4 b1 = *(const float4*)(Wp + (long long)(bk + 8) * D_ + bn);
    As[0][ak+0][am] = a0.x; As[0][ak+1][am] = a0.y; As[0][ak+2][am] = a0.z; As[0][ak+3][am] = a0.w;
    As[0][ak+8][am] = a1.x; As[0][ak+9][am] = a1.y; As[0][ak+10][am] = a1.z; As[0][ak+11][am] = a1.w;
    *(float4*)&Bs[0][bk][bn] = b0;
    *(float4*)&Bs[0][bk+8][bn] = b1;
    __syncthreads();

    int buf = 0;
    for (int k0 = 0; k0 < D_; k0 += 16) {
        int kn = k0 + 16;
        if (kn < D_) {
            a0 = *(const float4*)(Ap + kn + ak);
            a1 = *(const float4*)(Ap + kn + ak + 8);
            b0 = *(const float4*)(Wp + (long long)(kn + bk) * D_ + bn);
            b1 = *(const float4*)(Wp + (long long)(kn + bk + 8) * D_ + bn);
        }
        #pragma unroll
        for (int kk = 0; kk < 16; kk++) {
            float4 x0 = *(const float4*)&As[buf][kk][ty4];
            float4 x1 = *(const float4*)&As[buf][kk][ty4 + 64];
            float4 y0 = *(const float4*)&Bs[buf][kk][tx4];
            float4 y1 = *(const float4*)&Bs[buf][kk][tx4 + 64];
            float ar[8] = {x0.x,x0.y,x0.z,x0.w,x1.x,x1.y,x1.z,x1.w};
            float br[8] = {y0.x,y0.y,y0.z,y0.w,y1.x,y1.y,y1.z,y1.w};
            #pragma unroll
            for (int ii = 0; ii < 8; ii++)
                #pragma unroll
                for (int jj = 0; jj < 8; jj++)
                    acc[ii][jj] = fmaf(ar[ii], br[jj], acc[ii][jj]);
        }
        if (kn < D_) {
            buf ^= 1;
            As[buf][ak+0][am] = a0.x; As[buf][ak+1][am] = a0.y;
            As[buf][ak+2][am] = a0.z; As[buf][ak+3][am] = a0.w;
            As[buf][ak+8][am] = a1.x; As[buf][ak+9][am] = a1.y;
            As[buf][ak+10][am] = a1.z; As[buf][ak+11][am] = a1.w;
            *(float4*)&Bs[buf][bk][bn] = b0;
            *(float4*)&Bs[buf][bk+8][bn] = b1;
        }
        __syncthreads();
    }

    float4 bs0 = *(const float4*)(bias + n0 + tx4);
    float4 bs1 = *(const float4*)(bias + n0 + 64 + tx4);
    #pragma unroll
    for (int ii = 0; ii < 8; ii++) {
        int row = m0 + ((ii < 4) ? (ty4 + ii) : (64 + ty4 + ii - 4));
        float4 o0 = make_float4(acc[ii][0]+bs0.x, acc[ii][1]+bs0.y, acc[ii][2]+bs0.z, acc[ii][3]+bs0.w);
        float4 o1 = make_float4(acc[ii][4]+bs1.x, acc[ii][5]+bs1.y, acc[ii][6]+bs1.z, acc[ii][7]+bs1.w);
        *(float4*)(C + (long long)row * D_ + n0 + tx4)      = o0;
        *(float4*)(C + (long long)row * D_ + n0 + 64 + tx4) = o1;
    }
}

// ---------------- fused flash attention ------------------------------------
// Block = (128 q rows, one (b,h)). Loops 4 j-tiles of 128.
// p = gfac * exp(s - m_running); O = sum p*V / l.
#define VST 68
#define PST 132

__device__ __forceinline__ float rmax16(float v) {
    v = fmaxf(v, __shfl_xor_sync(0xffffffffu, v, 8, 16));
    v = fmaxf(v, __shfl_xor_sync(0xffffffffu, v, 4, 16));
    v = fmaxf(v, __shfl_xor_sync(0xffffffffu, v, 2, 16));
    v = fmaxf(v, __shfl_xor_sync(0xffffffffu, v, 1, 16));
    return v;
}
__device__ __forceinline__ float rsum16(float v) {
    v += __shfl_xor_sync(0xffffffffu, v, 8, 16);
    v += __shfl_xor_sync(0xffffffffu, v, 4, 16);
    v += __shfl_xor_sync(0xffffffffu, v, 2, 16);
    v += __shfl_xor_sync(0xffffffffu, v, 1, 16);
    return v;
}

__global__ void __launch_bounds__(256) flash_kernel(const int* __restrict__ msk) {
    extern __shared__ float sm[];
    float* Qs = sm;                   // [64][128]
    float* Ks = sm + 8192;            // [64][128]
    float* Vs = sm + 16384;           // [128][VST]
    float* Ps = sm + 16384 + 128*VST; // [128][PST]

    int t = threadIdx.x;
    int ty4 = (t >> 4) << 2, tx4 = (t & 15) << 2;
    int i0 = blockIdx.x << 7;
    int h  = blockIdx.y;
    int b  = blockIdx.z;
    const float* Qg = g_q + (long long)b * N_ * D_ + h * DK_;
    const float* Kg = g_k + (long long)b * N_ * D_ + h * DK_;
    const float* Vg = g_v + (long long)b * N_ * D_ + h * DK_;
    const float* Fg = g_F + ((long long)(b * H_ + h)) * NN_ + (long long)i0 * N_;
    float* AOg = g_ao + (long long)b * N_ * D_ + h * DK_;
    const int* mrow = msk + b * N_;

    // load Q tile transposed: Qs[d][i]
    {
        int qi = t & 127;
        int qd0 = (t >> 7) << 2;
        const float* src = Qg + (long long)(i0 + qi) * D_;
        #pragma unroll
        for (int it = 0; it < 8; it++) {
            int d = qd0 + it * 8;
            float4 u = *(const float4*)(src + d);
            Qs[(d+0)*128 + qi] = u.x;
            Qs[(d+1)*128 + qi] = u.y;
            Qs[(d+2)*128 + qi] = u.z;
            Qs[(d+3)*128 + qi] = u.w;
        }
    }

    float O[8][4];
    float m8[8], l8[8];
    #pragma unroll
    for (int i = 0; i < 8; i++) {
        m8[i] = -1e30f; l8[i] = 0.0f;
        O[i][0] = O[i][1] = O[i][2] = O[i][3] = 0.0f;
    }
    int prow[8];
    #pragma unroll
    for (int ii = 0; ii < 8; ii++)
        prow[ii] = ((ii < 4) ? (ty4 + ii) : (64 + ty4 + ii - 4)) * PST;

    #pragma unroll 1
    for (int jt = 0; jt < 4; jt++) {
        int j0 = jt << 7;
        __syncthreads();   // prev PV done before overwriting Ks/Vs; covers Qs on jt=0
        // K tile transposed
        {
            int kj = t & 127;
            int kd0 = (t >> 7) << 2;
            const float* src = Kg + (long long)(j0 + kj) * D_;
            #pragma unroll
            for (int it = 0; it < 8; it++) {
                int d = kd0 + it * 8;
                float4 u = *(const float4*)(src + d);
                Ks[(d+0)*128 + kj] = u.x;
                Ks[(d+1)*128 + kj] = u.y;
                Ks[(d+2)*128 + kj] = u.z;
                Ks[(d+3)*128 + kj] = u.w;
            }
        }
        // V tile direct
        {
            int vc = (t & 15) << 2;
            int vj = t >> 4;
            #pragma unroll
            for (int it = 0; it < 8; it++) {
                int j = vj + it * 16;
                *(float4*)&Vs[j * VST + vc] =
                    *(const float4*)(Vg + (long long)(j0 + j) * D_ + vc);
            }
        }
        __syncthreads();

        // S = Q @ K^T
        float S[8][8];
        #pragma unroll
        for (int i = 0; i < 8; i++)
            #pragma unroll
            for (int j = 0; j < 8; j++) S[i][j] = 0.0f;
        #pragma unroll 8
        for (int d = 0; d < 64; d++) {
            float4 q0 = *(const float4*)&Qs[d*128 + ty4];
            float4 q1 = *(const float4*)&Qs[d*128 + ty4 + 64];
            float4 k0 = *(const float4*)&Ks[d*128 + tx4];
            float4 k1 = *(const float4*)&Ks[d*128 + tx4 + 64];
            float qa[8] = {q0.x,q0.y,q0.z,q0.w,q1.x,q1.y,q1.z,q1.w};
            float kb[8] = {k0.x,k0.y,k0.z,k0.w,k1.x,k1.y,k1.z,k1.w};
            #pragma unroll
            for (int ii = 0; ii < 8; ii++)
                #pragma unroll
                for (int jj = 0; jj < 8; jj++)
                    S[ii][jj] = fmaf(qa[ii], kb[jj], S[ii][jj]);
        }

        // scale + mask
        int mc[8];
        #pragma unroll
        for (int jj = 0; jj < 8; jj++) {
            int cj = (jj < 4) ? (j0 + tx4 + jj) : (j0 + 64 + tx4 + jj - 4);
            mc[jj] = mrow[cj];
        }
        #pragma unroll
        for (int ii = 0; ii < 8; ii++)
            #pragma unroll
            for (int jj = 0; jj < 8; jj++) {
                float s = S[ii][jj] * 0.125f;
                S[ii][jj] = mc[jj] ? s : -1e9f;
            }

        // online softmax update
        #pragma unroll
        for (int ii = 0; ii < 8; ii++) {
            float mx = S[ii][0];
            #pragma unroll
            for (int jj = 1; jj < 8; jj++) mx = fmaxf(mx, S[ii][jj]);
            mx = rmax16(mx);
            float mnew = fmaxf(m8[ii], mx);
            float fac = __expf(m8[ii] - mnew);
            m8[ii] = mnew;
            l8[ii] *= fac;
            O[ii][0] *= fac; O[ii][1] *= fac; O[ii][2] *= fac; O[ii][3] *= fac;
        }

        // p = F * exp(s - m); accumulate l
        #pragma unroll
        for (int ii = 0; ii < 8; ii++) {
            int ig = (ii < 4) ? (ty4 + ii) : (64 + ty4 + ii - 4);
            const float* fr = Fg + (long long)ig * N_ + j0;
            float4 f0 = *(const float4*)(fr + tx4);
            float4 f1 = *(const float4*)(fr + 64 + tx4);
            float m = m8[ii];
            S[ii][0] = f0.x * __expf(S[ii][0] - m);
            S[ii][1] = f0.y * __expf(S[ii][1] - m);
            S[ii][2] = f0.z * __expf(S[ii][2] - m);
            S[ii][3] = f0.w * __expf(S[ii][3] - m);
            S[ii][4] = f1.x * __expf(S[ii][4] - m);
            S[ii][5] = f1.y * __expf(S[ii][5] - m);
            S[ii][6] = f1.z * __expf(S[ii][6] - m);
            S[ii][7] = f1.w * __expf(S[ii][7] - m);
            float rs = S[ii][0]+S[ii][1]+S[ii][2]+S[ii][3]
                     + S[ii][4]+S[ii][5]+S[ii][6]+S[ii][7];
            l8[ii] += rsum16(rs);
        }

        // store P row-major [i][PST] (conflict-free float4 along j)
        #pragma unroll
        for (int ii = 0; ii < 8; ii++) {
            *(float4*)&Ps[prow[ii] + tx4]      = make_float4(S[ii][0], S[ii][1], S[ii][2], S[ii][3]);
            *(float4*)&Ps[prow[ii] + 64 + tx4] = make_float4(S[ii][4], S[ii][5], S[ii][6], S[ii][7]);
        }
        __syncthreads();

        // O += P @ V
        #pragma unroll 4
        for (int j = 0; j < 128; j += 4) {
            float4 v0 = *(const float4*)&Vs[(j+0)*VST + tx4];
            float4 v1 = *(const float4*)&Vs[(j+1)*VST + tx4];
            float4 v2 = *(const float4*)&Vs[(j+2)*VST + tx4];
            float4 v3 = *(const float4*)&Vs[(j+3)*VST + tx4];
            #pragma unroll
            for (int ii = 0; ii < 8; ii++) {
                float4 p = *(const float4*)&Ps[prow[ii] + j];
                O[ii][0] = fmaf(p.x, v0.x, O[ii][0]);
                O[ii][1] = fmaf(p.x, v0.y, O[ii][1]);
                O[ii][2] = fmaf(p.x, v0.z, O[ii][2]);
                O[ii][3] = fmaf(p.x, v0.w, O[ii][3]);
                O[ii][0] = fmaf(p.y, v1.x, O[ii][0]);
                O[ii][1] = fmaf(p.y, v1.y, O[ii][1]);
                O[ii][2] = fmaf(p.y, v1.z, O[ii][2]);
                O[ii][3] = fmaf(p.y, v1.w, O[ii][3]);
                O[ii][0] = fmaf(p.z, v2.x, O[ii][0]);
                O[ii][1] = fmaf(p.z, v2.y, O[ii][1]);
                O[ii][2] = fmaf(p.z, v2.z, O[ii][2]);
                O[ii][3] = fmaf(p.z, v2.w, O[ii][3]);
                O[ii][0] = fmaf(p.w, v3.x, O[ii][0]);
                O[ii][1] = fmaf(p.w, v3.y, O[ii][1]);
                O[ii][2] = fmaf(p.w, v3.z, O[ii][2]);
                O[ii][3] = fmaf(p.w, v3.w, O[ii][3]);
            }
        }
    }

    #pragma unroll
    for (int ii = 0; ii < 8; ii++) {
        int ig = i0 + ((ii < 4) ? (ty4 + ii) : (64 + ty4 + ii - 4));
        float inv = 1.0f / l8[ii];
        float4 o = make_float4(O[ii][0]*inv, O[ii][1]*inv, O[ii][2]*inv, O[ii][3]*inv);
        *(float4*)(AOg + (long long)ig * D_ + tx4) = o;
    }
}

#define FLASH_SMEM ((16384 + 128*VST + 128*PST) * 4)

// ---------------- launch ----------------------------------------------------
extern "C" void kernel_launch(void* const* d_in, const int* in_sizes, int n_in,
                              void* d_out, int out_size) {
    const float* inq = (const float*)d_in[0];
    const float* ink = (const float*)d_in[1];
    const float* inv = (const float*)d_in[2];
    const float* box = (const float*)d_in[3];
    const int*   msk = (const int*)d_in[4];
    const void*  nob = d_in[5];
    const float* Wq = (const float*)d_in[6];  const float* bq = (const float*)d_in[7];
    const float* Wk = (const float*)d_in[8];  const float* bk = (const float*)d_in[9];
    const float* Wv = (const float*)d_in[10]; const float* bv = (const float*)d_in[11];
    const float* Wo = (const float*)d_in[12]; const float* bo = (const float*)d_in[13];
    const float* WG = (const float*)d_in[14]; const float* bG = (const float*)d_in[15];
    float* out = (float*)d_out;

    float *pq, *pk, *pv, *pao;
    cudaGetSymbolAddress((void**)&pq,  g_q);
    cudaGetSymbolAddress((void**)&pk,  g_k);
    cudaGetSymbolAddress((void**)&pv,  g_v);
    cudaGetSymbolAddress((void**)&pao, g_ao);

    cudaFuncSetAttribute(flash_kernel, cudaFuncAttributeMaxDynamicSharedMemorySize, FLASH_SMEM);

    detect_nobj<<<1, 256>>>((const int*)nob);
    box_pre<<<32, 128>>>(box, nob);
    geom_kernel<<<BNT, 128>>>(WG, bG);

    dim3 gP(4, 32, 1);   // 4096x512x512, 128x128 tiles
    proj_gemm<<<gP, 256>>>(inq, Wq, bq, pq);
    proj_gemm<<<gP, 256>>>(ink, Wk, bk, pk);
    proj_gemm<<<gP, 256>>>(inv, Wv, bv, pv);

    flash_kernel<<<dim3(4, H_, B_), 256, FLASH_SMEM>>>(msk);

    proj_gemm<<<gP, 256>>>(pao, Wo, bo, out);
}

// round 4
// speedup vs baseline: 1.1857x; 1.0912x over previous
#include <cuda_runtime.h>
#include <math.h>

#define B_ 8
#define N_ 512
#define D_ 512
#define H_ 8
#define DK_ 64
#define BNT 4096                 // B*N
#define NN_ 262144               // N*N

// ---------------- scratch (static device globals; no allocation allowed) ----
__device__ float g_q [BNT * D_];
__device__ float g_k [BNT * D_];
__device__ float g_v [BNT * D_];
__device__ float g_ao[BNT * D_];
__device__ float g_F [(long long)B_ * H_ * NN_];   // geometry factor gfac
__device__ float g_cx[BNT], g_cy[BNT], g_lw[BNT], g_lh[BNT], g_iw[BNT], g_ih[BNT], g_no[BNT];
__device__ int   g_isbyte;

// 100 / 1000^(m/8)
__constant__ float c_DM[8] = {
    100.0f, 42.169650342858224f, 17.78279410038923f, 7.498942093324559f,
    3.1622776601683795f, 1.3335214321633242f, 0.5623413251903491f, 0.23713737056616555f};

// ---------------- detect layout of not_objects (bool-as-int32 vs bytes) ----
__global__ void detect_nobj(const int* __restrict__ p) {
    __shared__ int bad[256];
    int t = threadIdx.x;
    int v = 0;
    for (int i = t; i < 1024; i += 256) {
        int x = p[i];
        v |= (x != 0 && x != 1);
    }
    bad[t] = v;
    __syncthreads();
    for (int s = 128; s; s >>= 1) {
        if (t < s) bad[t] |= bad[t + s];
        __syncthreads();
    }
    if (t == 0) g_isbyte = bad[0];
}

// ---------------- per-box precompute ---------------------------------------
__global__ void box_pre(const float* __restrict__ box, const void* __restrict__ nobj) {
    int i = blockIdx.x * blockDim.x + threadIdx.x;
    if (i >= BNT) return;
    float x0 = box[4*i+0], y0 = box[4*i+1], x1 = box[4*i+2], y1 = box[4*i+3];
    float w = x1 - x0 + 1.0f, h = y1 - y0 + 1.0f;
    g_cx[i] = 0.5f * (x0 + x1);
    g_cy[i] = 0.5f * (y0 + y1);
    g_lw[i] = logf(w);
    g_lh[i] = logf(h);
    g_iw[i] = 1.0f / w;
    g_ih[i] = 1.0f / h;
    int nv = g_isbyte ? (int)((const unsigned char*)nobj)[i]
                      : ((const int*)nobj)[i];
    g_no[i] = nv ? 1.0f : 0.0f;
}

// Cody-Waite reduced fast sincos: accurate for |x| up to ~800.
__device__ __forceinline__ void fsincos(float x, float& s, float& c) {
    float k = rintf(x * 0.15915494309189535f);
    float r = __fmaf_rn(k, -6.28125f, x);
    r = __fmaf_rn(k, -1.9353071795864769e-3f, r);
    s = __sinf(r);
    c = __cosf(r);
}

// ---------------- geometry factor: gfac[b,h,i,j] ---------------------------
__global__ void __launch_bounds__(128) geom_kernel(const float* __restrict__ WG,
                                                   const float* __restrict__ bG) {
    __shared__ float sWs[32][8];
    __shared__ float sWc[32][8];
    __shared__ float sbG[8];
    int t = threadIdx.x;
    for (int x = t; x < 512; x += 128) {
        int h = x >> 6, g = x & 63;
        if (g < 32) sWs[g][h] = WG[x];
        else        sWc[g - 32][h] = WG[x];
    }
    if (t < 8) sbG[t] = bG[t];
    __syncthreads();

    int row = blockIdx.x;
    int b = row >> 9, i = row & 511;
    int base = b << 9;
    float cxi = g_cx[base + i], cyi = g_cy[base + i];
    float iwi = g_iw[base + i], ihi = g_ih[base + i];
    float lwi = g_lw[base + i], lhi = g_lh[base + i];
    float noi = g_no[base + i];

    for (int j = t; j < N_; j += 128) {
        int jj = base + j;
        float dx = __logf(fmaxf(fabsf(g_cx[jj] - cxi) * iwi, 1e-3f));
        float dy = __logf(fmaxf(fabsf(g_cy[jj] - cyi) * ihi, 1e-3f));
        float dw = lwi - g_lw[jj];
        float dh = lhi - g_lh[jj];
        float pos[4] = {dx, dy, dw, dh};

        float acc[8];
        #pragma unroll
        for (int h = 0; h < 8; h++) acc[h] = sbG[h];

        #pragma unroll
        for (int kk = 0; kk < 4; kk++) {
            #pragma unroll
            for (int m = 0; m < 8; m++) {
                float s, c;
                fsincos(pos[kk] * c_DM[m], s, c);
                int g = kk * 8 + m;
                float4 ws0 = *(const float4*)&sWs[g][0];
                float4 ws1 = *(const float4*)&sWs[g][4];
                float4 wc0 = *(const float4*)&sWc[g][0];
                float4 wc1 = *(const float4*)&sWc[g][4];
                acc[0] = fmaf(s, ws0.x, fmaf(c, wc0.x, acc[0]));
                acc[1] = fmaf(s, ws0.y, fmaf(c, wc0.y, acc[1]));
                acc[2] = fmaf(s, ws0.z, fmaf(c, wc0.z, acc[2]));
                acc[3] = fmaf(s, ws0.w, fmaf(c, wc0.w, acc[3]));
                acc[4] = fmaf(s, ws1.x, fmaf(c, wc1.x, acc[4]));
                acc[5] = fmaf(s, ws1.y, fmaf(c, wc1.y, acc[5]));
                acc[6] = fmaf(s, ws1.z, fmaf(c, wc1.z, acc[6]));
                acc[7] = fmaf(s, ws1.w, fmaf(c, wc1.w, acc[7]));
            }
        }
        bool obj = (fmaxf(noi, g_no[jj]) < 0.5f);
        long long o = (long long)b * H_ * NN_ + (long long)i * N_ + j;
        #pragma unroll
        for (int h = 0; h < 8; h++) {
            float gf = obj ? fmaxf(acc[h], 1e-6f) : 1.0f;
            g_F[o + (long long)h * NN_] = gf;
        }
    }
}

// ---------------- projection GEMM: C = A @ W + bias ------------------------
// 128x64 tiles, 256 threads, 8x4 per thread (quad rows), double-buffered.
// blockIdx.z selects among up to 3 (A, W, bias, C) problem tuples.
__global__ void __launch_bounds__(256, 2) proj_gemm(
    const float* __restrict__ A0, const float* __restrict__ A1, const float* __restrict__ A2,
    const float* __restrict__ W0, const float* __restrict__ W1, const float* __restrict__ W2,
    const float* __restrict__ b0p, const float* __restrict__ b1p, const float* __restrict__ b2p,
    float* __restrict__ C0, float* __restrict__ C1, float* __restrict__ C2)
{
    int z = blockIdx.z;
    const float* A = (z == 0) ? A0 : (z == 1) ? A1 : A2;
    const float* W = (z == 0) ? W0 : (z == 1) ? W1 : W2;
    const float* bias = (z == 0) ? b0p : (z == 1) ? b1p : b2p;
    float* C = (z == 0) ? C0 : (z == 1) ? C1 : C2;

    __shared__ float As[2][16][128];
    __shared__ float Bs[2][16][64];
    int t = threadIdx.x;
    int ty4 = (t >> 4) << 2, tx4 = (t & 15) << 2;
    int m0 = blockIdx.y << 7, n0 = blockIdx.x << 6;
    int am = t & 127, ak = (t >> 7) << 2;          // ak in {0,4}
    int bk = t >> 4,  bn = (t & 15) << 2;          // bk 0..15
    const float* Ap = A + (long long)(m0 + am) * D_;
    const float* Wp = W + n0;

    float acc[8][4];
    #pragma unroll
    for (int i = 0; i < 8; i++)
        #pragma unroll
        for (int j = 0; j < 4; j++) acc[i][j] = 0.0f;

    float4 a0 = *(const float4*)(Ap + ak);
    float4 a1 = *(const float4*)(Ap + ak + 8);
    float4 bb = *(const float4*)(Wp + (long long)bk * D_ + bn);
    As[0][ak+0][am] = a0.x; As[0][ak+1][am] = a0.y; As[0][ak+2][am] = a0.z; As[0][ak+3][am] = a0.w;
    As[0][ak+8][am] = a1.x; As[0][ak+9][am] = a1.y; As[0][ak+10][am] = a1.z; As[0][ak+11][am] = a1.w;
    *(float4*)&Bs[0][bk][bn] = bb;
    __syncthreads();

    int buf = 0;
    for (int k0 = 0; k0 < D_; k0 += 16) {
        int kn = k0 + 16;
        if (kn < D_) {
            a0 = *(const float4*)(Ap + kn + ak);
            a1 = *(const float4*)(Ap + kn + ak + 8);
            bb = *(const float4*)(Wp + (long long)(kn + bk) * D_ + bn);
        }
        #pragma unroll
        for (int kk = 0; kk < 16; kk++) {
            float4 x0 = *(const float4*)&As[buf][kk][ty4];
            float4 x1 = *(const float4*)&As[buf][kk][ty4 + 64];
            float4 y0 = *(const float4*)&Bs[buf][kk][tx4];
            float ar[8] = {x0.x,x0.y,x0.z,x0.w,x1.x,x1.y,x1.z,x1.w};
            float br[4] = {y0.x,y0.y,y0.z,y0.w};
            #pragma unroll
            for (int ii = 0; ii < 8; ii++)
                #pragma unroll
                for (int jj = 0; jj < 4; jj++)
                    acc[ii][jj] = fmaf(ar[ii], br[jj], acc[ii][jj]);
        }
        if (kn < D_) {
            buf ^= 1;
            As[buf][ak+0][am] = a0.x; As[buf][ak+1][am] = a0.y;
            As[buf][ak+2][am] = a0.z; As[buf][ak+3][am] = a0.w;
            As[buf][ak+8][am] = a1.x; As[buf][ak+9][am] = a1.y;
            As[buf][ak+10][am] = a1.z; As[buf][ak+11][am] = a1.w;
            *(float4*)&Bs[buf][bk][bn] = bb;
        }
        __syncthreads();
    }

    float4 bs0 = *(const float4*)(bias + n0 + tx4);
    #pragma unroll
    for (int ii = 0; ii < 8; ii++) {
        int row = m0 + ((ii < 4) ? (ty4 + ii) : (64 + ty4 + ii - 4));
        float4 o0 = make_float4(acc[ii][0]+bs0.x, acc[ii][1]+bs0.y, acc[ii][2]+bs0.z, acc[ii][3]+bs0.w);
        *(float4*)(C + (long long)row * D_ + n0 + tx4) = o0;
    }
}

// ---------------- fused flash attention ------------------------------------
// Block = (128 q rows, one (b,h)). Loops 4 j-tiles of 128.
// p = gfac * exp(s - m_running); O = sum p*V / l.
#define VST 68
#define PST 132

__device__ __forceinline__ float rmax16(float v) {
    v = fmaxf(v, __shfl_xor_sync(0xffffffffu, v, 8, 16));
    v = fmaxf(v, __shfl_xor_sync(0xffffffffu, v, 4, 16));
    v = fmaxf(v, __shfl_xor_sync(0xffffffffu, v, 2, 16));
    v = fmaxf(v, __shfl_xor_sync(0xffffffffu, v, 1, 16));
    return v;
}
__device__ __forceinline__ float rsum16(float v) {
    v += __shfl_xor_sync(0xffffffffu, v, 8, 16);
    v += __shfl_xor_sync(0xffffffffu, v, 4, 16);
    v += __shfl_xor_sync(0xffffffffu, v, 2, 16);
    v += __shfl_xor_sync(0xffffffffu, v, 1, 16);
    return v;
}

__global__ void __launch_bounds__(256) flash_kernel(const int* __restrict__ msk) {
    extern __shared__ float sm[];
    float* Qs = sm;                   // [64][128]
    float* Ks = sm + 8192;            // [64][128]
    float* Vs = sm + 16384;           // [128][VST]
    float* Ps = sm + 16384 + 128*VST; // [128][PST]

    int t = threadIdx.x;
    int ty4 = (t >> 4) << 2, tx4 = (t & 15) << 2;
    int i0 = blockIdx.x << 7;
    int h  = blockIdx.y;
    int b  = blockIdx.z;
    const float* Qg = g_q + (long long)b * N_ * D_ + h * DK_;
    const float* Kg = g_k + (long long)b * N_ * D_ + h * DK_;
    const float* Vg = g_v + (long long)b * N_ * D_ + h * DK_;
    const float* Fg = g_F + ((long long)(b * H_ + h)) * NN_ + (long long)i0 * N_;
    float* AOg = g_ao + (long long)b * N_ * D_ + h * DK_;
    const int* mrow = msk + b * N_;

    // load Q tile transposed, pre-scaled by 0.125: Qs[d][i]
    {
        int qi = t & 127;
        int qd0 = (t >> 7) << 2;
        const float* src = Qg + (long long)(i0 + qi) * D_;
        #pragma unroll
        for (int it = 0; it < 8; it++) {
            int d = qd0 + it * 8;
            float4 u = *(const float4*)(src + d);
            Qs[(d+0)*128 + qi] = u.x * 0.125f;
            Qs[(d+1)*128 + qi] = u.y * 0.125f;
            Qs[(d+2)*128 + qi] = u.z * 0.125f;
            Qs[(d+3)*128 + qi] = u.w * 0.125f;
        }
    }

    float O[8][4];
    float m8[8], l8[8];
    #pragma unroll
    for (int i = 0; i < 8; i++) {
        m8[i] = -1e30f; l8[i] = 0.0f;
        O[i][0] = O[i][1] = O[i][2] = O[i][3] = 0.0f;
    }
    int prow[8];
    #pragma unroll
    for (int ii = 0; ii < 8; ii++)
        prow[ii] = ((ii < 4) ? (ty4 + ii) : (64 + ty4 + ii - 4)) * PST;

    #pragma unroll 1
    for (int jt = 0; jt < 4; jt++) {
        int j0 = jt << 7;
        __syncthreads();   // prev PV done before overwriting Ks/Vs; covers Qs on jt=0
        // K tile transposed
        {
            int kj = t & 127;
            int kd0 = (t >> 7) << 2;
            const float* src = Kg + (long long)(j0 + kj) * D_;
            #pragma unroll
            for (int it = 0; it < 8; it++) {
                int d = kd0 + it * 8;
                float4 u = *(const float4*)(src + d);
                Ks[(d+0)*128 + kj] = u.x;
                Ks[(d+1)*128 + kj] = u.y;
                Ks[(d+2)*128 + kj] = u.z;
                Ks[(d+3)*128 + kj] = u.w;
            }
        }
        // V tile direct
        {
            int vc = (t & 15) << 2;
            int vj = t >> 4;
            #pragma unroll
            for (int it = 0; it < 8; it++) {
                int j = vj + it * 16;
                *(float4*)&Vs[j * VST + vc] =
                    *(const float4*)(Vg + (long long)(j0 + j) * D_ + vc);
            }
        }
        __syncthreads();

        // S = Q @ K^T (Q pre-scaled)
        float S[8][8];
        #pragma unroll
        for (int i = 0; i < 8; i++)
            #pragma unroll
            for (int j = 0; j < 8; j++) S[i][j] = 0.0f;
        #pragma unroll 8
        for (int d = 0; d < 64; d++) {
            float4 q0 = *(const float4*)&Qs[d*128 + ty4];
            float4 q1 = *(const float4*)&Qs[d*128 + ty4 + 64];
            float4 k0 = *(const float4*)&Ks[d*128 + tx4];
            float4 k1 = *(const float4*)&Ks[d*128 + tx4 + 64];
            float qa[8] = {q0.x,q0.y,q0.z,q0.w,q1.x,q1.y,q1.z,q1.w};
            float kb[8] = {k0.x,k0.y,k0.z,k0.w,k1.x,k1.y,k1.z,k1.w};
            #pragma unroll
            for (int ii = 0; ii < 8; ii++)
                #pragma unroll
                for (int jj = 0; jj < 8; jj++)
                    S[ii][jj] = fmaf(qa[ii], kb[jj], S[ii][jj]);
        }

        // mask
        int mc[8];
        #pragma unroll
        for (int jj = 0; jj < 8; jj++) {
            int cj = (jj < 4) ? (j0 + tx4 + jj) : (j0 + 64 + tx4 + jj - 4);
            mc[jj] = mrow[cj];
        }
        #pragma unroll
        for (int ii = 0; ii < 8; ii++)
            #pragma unroll
            for (int jj = 0; jj < 8; jj++)
                S[ii][jj] = mc[jj] ? S[ii][jj] : -1e9f;

        // online softmax update
        #pragma unroll
        for (int ii = 0; ii < 8; ii++) {
            float mx = S[ii][0];
            #pragma unroll
            for (int jj = 1; jj < 8; jj++) mx = fmaxf(mx, S[ii][jj]);
            mx = rmax16(mx);
            float mnew = fmaxf(m8[ii], mx);
            float fac = __expf(m8[ii] - mnew);
            m8[ii] = mnew;
            l8[ii] *= fac;
            O[ii][0] *= fac; O[ii][1] *= fac; O[ii][2] *= fac; O[ii][3] *= fac;
        }

        // p = F * exp(s - m); accumulate l
        #pragma unroll
        for (int ii = 0; ii < 8; ii++) {
            int ig = (ii < 4) ? (ty4 + ii) : (64 + ty4 + ii - 4);
            const float* fr = Fg + (long long)ig * N_ + j0;
            float4 f0 = *(const float4*)(fr + tx4);
            float4 f1 = *(const float4*)(fr + 64 + tx4);
            float m = m8[ii];
            S[ii][0] = f0.x * __expf(S[ii][0] - m);
            S[ii][1] = f0.y * __expf(S[ii][1] - m);
            S[ii][2] = f0.z * __expf(S[ii][2] - m);
            S[ii][3] = f0.w * __expf(S[ii][3] - m);
            S[ii][4] = f1.x * __expf(S[ii][4] - m);
            S[ii][5] = f1.y * __expf(S[ii][5] - m);
            S[ii][6] = f1.z * __expf(S[ii][6] - m);
            S[ii][7] = f1.w * __expf(S[ii][7] - m);
            float rs = S[ii][0]+S[ii][1]+S[ii][2]+S[ii][3]
                     + S[ii][4]+S[ii][5]+S[ii][6]+S[ii][7];
            l8[ii] += rsum16(rs);
        }

        // store P row-major [i][PST] (conflict-free float4 along j)
        #pragma unroll
        for (int ii = 0; ii < 8; ii++) {
            *(float4*)&Ps[prow[ii] + tx4]      = make_float4(S[ii][0], S[ii][1], S[ii][2], S[ii][3]);
            *(float4*)&Ps[prow[ii] + 64 + tx4] = make_float4(S[ii][4], S[ii][5], S[ii][6], S[ii][7]);
        }
        __syncthreads();

        // O += P @ V
        #pragma unroll 4
        for (int j = 0; j < 128; j += 4) {
            float4 v0 = *(const float4*)&Vs[(j+0)*VST + tx4];
            float4 v1 = *(const float4*)&Vs[(j+1)*VST + tx4];
            float4 v2 = *(const float4*)&Vs[(j+2)*VST + tx4];
            float4 v3 = *(const float4*)&Vs[(j+3)*VST + tx4];
            #pragma unroll
            for (int ii = 0; ii < 8; ii++) {
                float4 p = *(const float4*)&Ps[prow[ii] + j];
                O[ii][0] = fmaf(p.x, v0.x, O[ii][0]);
                O[ii][1] = fmaf(p.x, v0.y, O[ii][1]);
                O[ii][2] = fmaf(p.x, v0.z, O[ii][2]);
                O[ii][3] = fmaf(p.x, v0.w, O[ii][3]);
                O[ii][0] = fmaf(p.y, v1.x, O[ii][0]);
                O[ii][1] = fmaf(p.y, v1.y, O[ii][1]);
                O[ii][2] = fmaf(p.y, v1.z, O[ii][2]);
                O[ii][3] = fmaf(p.y, v1.w, O[ii][3]);
                O[ii][0] = fmaf(p.z, v2.x, O[ii][0]);
                O[ii][1] = fmaf(p.z, v2.y, O[ii][1]);
                O[ii][2] = fmaf(p.z, v2.z, O[ii][2]);
                O[ii][3] = fmaf(p.z, v2.w, O[ii][3]);
                O[ii][0] = fmaf(p.w, v3.x, O[ii][0]);
                O[ii][1] = fmaf(p.w, v3.y, O[ii][1]);
                O[ii][2] = fmaf(p.w, v3.z, O[ii][2]);
                O[ii][3] = fmaf(p.w, v3.w, O[ii][3]);
            }
        }
    }

    #pragma unroll
    for (int ii = 0; ii < 8; ii++) {
        int ig = i0 + ((ii < 4) ? (ty4 + ii) : (64 + ty4 + ii - 4));
        float inv = 1.0f / l8[ii];
        float4 o = make_float4(O[ii][0]*inv, O[ii][1]*inv, O[ii][2]*inv, O[ii][3]*inv);
        *(float4*)(AOg + (long long)ig * D_ + tx4) = o;
    }
}

#define FLASH_SMEM ((16384 + 128*VST + 128*PST) * 4)

// ---------------- launch ----------------------------------------------------
extern "C" void kernel_launch(void* const* d_in, const int* in_sizes, int n_in,
                              void* d_out, int out_size) {
    const float* inq = (const float*)d_in[0];
    const float* ink = (const float*)d_in[1];
    const float* inv = (const float*)d_in[2];
    const float* box = (const float*)d_in[3];
    const int*   msk = (const int*)d_in[4];
    const void*  nob = d_in[5];
    const float* Wq = (const float*)d_in[6];  const float* bq = (const float*)d_in[7];
    const float* Wk = (const float*)d_in[8];  const float* bk = (const float*)d_in[9];
    const float* Wv = (const float*)d_in[10]; const float* bv = (const float*)d_in[11];
    const float* Wo = (const float*)d_in[12]; const float* bo = (const float*)d_in[13];
    const float* WG = (const float*)d_in[14]; const float* bG = (const float*)d_in[15];
    float* out = (float*)d_out;

    float *pq, *pk, *pv, *pao;
    cudaGetSymbolAddress((void**)&pq,  g_q);
    cudaGetSymbolAddress((void**)&pk,  g_k);
    cudaGetSymbolAddress((void**)&pv,  g_v);
    cudaGetSymbolAddress((void**)&pao, g_ao);

    cudaFuncSetAttribute(flash_kernel, cudaFuncAttributeMaxDynamicSharedMemorySize, FLASH_SMEM);

    detect_nobj<<<1, 256>>>((const int*)nob);
    box_pre<<<32, 128>>>(box, nob);
    geom_kernel<<<BNT, 128>>>(WG, bG);

    // QKV projections in one launch: grid (8 n-tiles, 32 m-tiles, 3 problems)
    dim3 gQKV(8, 32, 3);
    proj_gemm<<<gQKV, 256>>>(inq, ink, inv,
                             Wq, Wk, Wv,
                             bq, bk, bv,
                             pq, pk, pv);

    flash_kernel<<<dim3(4, H_, B_), 256, FLASH_SMEM>>>(msk);

    // output projection
    dim3 gO(8, 32, 1);
    proj_gemm<<<gO, 256>>>(pao, pao, pao,
                           Wo, Wo, Wo,
                           bo, bo, bo,
                           out, out, out);
}

// round 5
// speedup vs baseline: 1.2519x; 1.0558x over previous
#include <cuda_runtime.h>
#include <math.h>
#include <stdint.h>

#define B_ 8
#define N_ 512
#define D_ 512
#define H_ 8
#define DK_ 64
#define BNT 4096                 // B*N
#define NN_ 262144               // N*N

// ---------------- scratch (static device globals; no allocation allowed) ----
__device__ float g_q [BNT * D_];
__device__ float g_k [BNT * D_];
__device__ float g_v [BNT * D_];
__device__ float g_ao[BNT * D_];
__device__ float g_F [(long long)B_ * H_ * NN_];   // geometry factor gfac
__device__ float g_cx[BNT], g_cy[BNT], g_lw[BNT], g_lh[BNT], g_iw[BNT], g_ih[BNT], g_no[BNT];
__device__ int   g_isbyte;

// 100 / 1000^(m/8)
__constant__ float c_DM[8] = {
    100.0f, 42.169650342858224f, 17.78279410038923f, 7.498942093324559f,
    3.1622776601683795f, 1.3335214321633242f, 0.5623413251903491f, 0.23713737056616555f};

// ---------------- detect layout of not_objects (bool-as-int32 vs bytes) ----
__global__ void detect_nobj(const int* __restrict__ p) {
    __shared__ int bad[256];
    int t = threadIdx.x;
    int v = 0;
    for (int i = t; i < 1024; i += 256) {
        int x = p[i];
        v |= (x != 0 && x != 1);
    }
    bad[t] = v;
    __syncthreads();
    for (int s = 128; s; s >>= 1) {
        if (t < s) bad[t] |= bad[t + s];
        __syncthreads();
    }
    if (t == 0) g_isbyte = bad[0];
}

// ---------------- per-box precompute ---------------------------------------
__global__ void box_pre(const float* __restrict__ box, const void* __restrict__ nobj) {
    int i = blockIdx.x * blockDim.x + threadIdx.x;
    if (i >= BNT) return;
    float x0 = box[4*i+0], y0 = box[4*i+1], x1 = box[4*i+2], y1 = box[4*i+3];
    float w = x1 - x0 + 1.0f, h = y1 - y0 + 1.0f;
    g_cx[i] = 0.5f * (x0 + x1);
    g_cy[i] = 0.5f * (y0 + y1);
    g_lw[i] = logf(w);
    g_lh[i] = logf(h);
    g_iw[i] = 1.0f / w;
    g_ih[i] = 1.0f / h;
    int nv = g_isbyte ? (int)((const unsigned char*)nobj)[i]
                      : ((const int*)nobj)[i];
    g_no[i] = nv ? 1.0f : 0.0f;
}

// Cody-Waite reduced fast sincos: accurate for |x| up to ~800.
__device__ __forceinline__ void fsincos(float x, float& s, float& c) {
    float k = rintf(x * 0.15915494309189535f);
    float r = __fmaf_rn(k, -6.28125f, x);
    r = __fmaf_rn(k, -1.9353071795864769e-3f, r);
    s = __sinf(r);
    c = __cosf(r);
}

// ---------------- geometry factor: gfac[b,h,i,j] ---------------------------
__global__ void __launch_bounds__(128) geom_kernel(const float* __restrict__ WG,
                                                   const float* __restrict__ bG) {
    __shared__ float sWs[32][8];
    __shared__ float sWc[32][8];
    __shared__ float sbG[8];
    int t = threadIdx.x;
    for (int x = t; x < 512; x += 128) {
        int h = x >> 6, g = x & 63;
        if (g < 32) sWs[g][h] = WG[x];
        else        sWc[g - 32][h] = WG[x];
    }
    if (t < 8) sbG[t] = bG[t];
    __syncthreads();

    int row = blockIdx.x;
    int b = row >> 9, i = row & 511;
    int base = b << 9;
    float cxi = g_cx[base + i], cyi = g_cy[base + i];
    float iwi = g_iw[base + i], ihi = g_ih[base + i];
    float lwi = g_lw[base + i], lhi = g_lh[base + i];
    float noi = g_no[base + i];

    for (int j = t; j < N_; j += 128) {
        int jj = base + j;
        float dx = __logf(fmaxf(fabsf(g_cx[jj] - cxi) * iwi, 1e-3f));
        float dy = __logf(fmaxf(fabsf(g_cy[jj] - cyi) * ihi, 1e-3f));
        float dw = lwi - g_lw[jj];
        float dh = lhi - g_lh[jj];
        float pos[4] = {dx, dy, dw, dh};

        float acc[8];
        #pragma unroll
        for (int h = 0; h < 8; h++) acc[h] = sbG[h];

        #pragma unroll
        for (int kk = 0; kk < 4; kk++) {
            #pragma unroll
            for (int m = 0; m < 8; m++) {
                float s, c;
                fsincos(pos[kk] * c_DM[m], s, c);
                int g = kk * 8 + m;
                float4 ws0 = *(const float4*)&sWs[g][0];
                float4 ws1 = *(const float4*)&sWs[g][4];
                float4 wc0 = *(const float4*)&sWc[g][0];
                float4 wc1 = *(const float4*)&sWc[g][4];
                acc[0] = fmaf(s, ws0.x, fmaf(c, wc0.x, acc[0]));
                acc[1] = fmaf(s, ws0.y, fmaf(c, wc0.y, acc[1]));
                acc[2] = fmaf(s, ws0.z, fmaf(c, wc0.z, acc[2]));
                acc[3] = fmaf(s, ws0.w, fmaf(c, wc0.w, acc[3]));
                acc[4] = fmaf(s, ws1.x, fmaf(c, wc1.x, acc[4]));
                acc[5] = fmaf(s, ws1.y, fmaf(c, wc1.y, acc[5]));
                acc[6] = fmaf(s, ws1.z, fmaf(c, wc1.z, acc[6]));
                acc[7] = fmaf(s, ws1.w, fmaf(c, wc1.w, acc[7]));
            }
        }
        bool obj = (fmaxf(noi, g_no[jj]) < 0.5f);
        long long o = (long long)b * H_ * NN_ + (long long)i * N_ + j;
        #pragma unroll
        for (int h = 0; h < 8; h++) {
            float gf = obj ? fmaxf(acc[h], 1e-6f) : 1.0f;
            g_F[o + (long long)h * NN_] = gf;
        }
    }
}

// ---------------- 3xTF32 helpers -------------------------------------------
__device__ __forceinline__ uint32_t cvt_tf32(float f) {
    uint32_t r;
    asm("cvt.rna.tf32.f32 %0, %1;" : "=r"(r) : "f"(f));
    return r;
}
__device__ __forceinline__ void split_tf32(float f, uint32_t& hi, uint32_t& lo) {
    hi = cvt_tf32(f);
    lo = cvt_tf32(f - __uint_as_float(hi));
}
__device__ __forceinline__ void mma_tf32(float* d, const uint32_t* a, const uint32_t* b) {
    asm("mma.sync.aligned.m16n8k8.row.col.f32.tf32.tf32.f32 "
        "{%0,%1,%2,%3}, {%4,%5,%6,%7}, {%8,%9}, {%0,%1,%2,%3};"
        : "+f"(d[0]), "+f"(d[1]), "+f"(d[2]), "+f"(d[3])
        : "r"(a[0]), "r"(a[1]), "r"(a[2]), "r"(a[3]), "r"(b[0]), "r"(b[1]));
}

// ---------------- projection GEMM (3xTF32 tensor core) ---------------------
// 128x64 block tile, 256 threads = 8 warps (4 m x 2 n), warp tile 32x32.
// Double-buffered fp32 smem tiles; fragments split hi/lo tf32 in registers.
#define AST 136   // As row stride (pad 8 -> conflict-free fragment gathers)
#define BST 72    // Bs row stride
__global__ void __launch_bounds__(256, 2) proj_gemm(
    const float* __restrict__ A0, const float* __restrict__ A1, const float* __restrict__ A2,
    const float* __restrict__ W0, const float* __restrict__ W1, const float* __restrict__ W2,
    const float* __restrict__ b0p, const float* __restrict__ b1p, const float* __restrict__ b2p,
    float* __restrict__ C0, float* __restrict__ C1, float* __restrict__ C2)
{
    int z = blockIdx.z;
    const float* A = (z == 0) ? A0 : (z == 1) ? A1 : A2;
    const float* W = (z == 0) ? W0 : (z == 1) ? W1 : W2;
    const float* bias = (z == 0) ? b0p : (z == 1) ? b1p : b2p;
    float* C = (z == 0) ? C0 : (z == 1) ? C1 : C2;

    __shared__ float As[2][16][AST];
    __shared__ float Bs[2][16][BST];
    int t = threadIdx.x;
    int lane = t & 31, wid = t >> 5;
    int wm = (wid & 3) << 5;          // warp m base (0,32,64,96)
    int wn = (wid >> 2) << 5;         // warp n base (0,32)
    int m0 = blockIdx.y << 7, n0 = blockIdx.x << 6;
    int am = t & 127, ak = (t >> 7) << 2;          // ak in {0,4}
    int bk = t >> 4,  bn = (t & 15) << 2;          // bk 0..15
    const float* Ap = A + (long long)(m0 + am) * D_;
    const float* Wp = W + n0;

    float acc[2][4][4];
    #pragma unroll
    for (int i = 0; i < 2; i++)
        #pragma unroll
        for (int j = 0; j < 4; j++)
            #pragma unroll
            for (int r = 0; r < 4; r++) acc[i][j][r] = 0.0f;

    int frow = lane >> 2, fcol = lane & 3;   // fragment row/col components

    float4 a0 = *(const float4*)(Ap + ak);
    float4 a1 = *(const float4*)(Ap + ak + 8);
    float4 bb = *(const float4*)(Wp + (long long)bk * D_ + bn);
    As[0][ak+0][am] = a0.x; As[0][ak+1][am] = a0.y; As[0][ak+2][am] = a0.z; As[0][ak+3][am] = a0.w;
    As[0][ak+8][am] = a1.x; As[0][ak+9][am] = a1.y; As[0][ak+10][am] = a1.z; As[0][ak+11][am] = a1.w;
    *(float4*)&Bs[0][bk][bn] = bb;
    __syncthreads();

    int buf = 0;
    for (int k0 = 0; k0 < D_; k0 += 16) {
        int kn = k0 + 16;
        if (kn < D_) {
            a0 = *(const float4*)(Ap + kn + ak);
            a1 = *(const float4*)(Ap + kn + ak + 8);
            bb = *(const float4*)(Wp + (long long)(kn + bk) * D_ + bn);
        }
        #pragma unroll
        for (int ks = 0; ks < 16; ks += 8) {
            // A fragments: 2 m16k8 tiles, split hi/lo
            uint32_t ah[2][4], al[2][4];
            #pragma unroll
            for (int mt = 0; mt < 2; mt++) {
                int mb = wm + (mt << 4) + frow;
                float f0 = As[buf][ks + fcol][mb];
                float f1 = As[buf][ks + fcol][mb + 8];
                float f2 = As[buf][ks + fcol + 4][mb];
                float f3 = As[buf][ks + fcol + 4][mb + 8];
                split_tf32(f0, ah[mt][0], al[mt][0]);
                split_tf32(f1, ah[mt][1], al[mt][1]);
                split_tf32(f2, ah[mt][2], al[mt][2]);
                split_tf32(f3, ah[mt][3], al[mt][3]);
            }
            // B fragments: 4 k8n8 tiles, split hi/lo
            uint32_t bh[4][2], bl[4][2];
            #pragma unroll
            for (int nt = 0; nt < 4; nt++) {
                int nb = wn + (nt << 3) + frow;
                float f0 = Bs[buf][ks + fcol][nb];
                float f1 = Bs[buf][ks + fcol + 4][nb];
                split_tf32(f0, bh[nt][0], bl[nt][0]);
                split_tf32(f1, bh[nt][1], bl[nt][1]);
            }
            #pragma unroll
            for (int mt = 0; mt < 2; mt++)
                #pragma unroll
                for (int nt = 0; nt < 4; nt++) {
                    mma_tf32(acc[mt][nt], ah[mt], bh[nt]);
                    mma_tf32(acc[mt][nt], ah[mt], bl[nt]);
                    mma_tf32(acc[mt][nt], al[mt], bh[nt]);
                }
        }
        if (kn < D_) {
            buf ^= 1;
            As[buf][ak+0][am] = a0.x; As[buf][ak+1][am] = a0.y;
            As[buf][ak+2][am] = a0.z; As[buf][ak+3][am] = a0.w;
            As[buf][ak+8][am] = a1.x; As[buf][ak+9][am] = a1.y;
            As[buf][ak+10][am] = a1.z; As[buf][ak+11][am] = a1.w;
            *(float4*)&Bs[buf][bk][bn] = bb;
        }
        __syncthreads();
    }

    // epilogue: c frag rows = frow, frow+8; cols = 2*fcol, 2*fcol+1
    #pragma unroll
    for (int mt = 0; mt < 2; mt++) {
        int row0 = m0 + wm + (mt << 4) + frow;
        #pragma unroll
        for (int nt = 0; nt < 4; nt++) {
            int col = n0 + wn + (nt << 3) + (fcol << 1);
            float bv0 = bias[col], bv1 = bias[col + 1];
            float2 u0 = make_float2(acc[mt][nt][0] + bv0, acc[mt][nt][1] + bv1);
            float2 u1 = make_float2(acc[mt][nt][2] + bv0, acc[mt][nt][3] + bv1);
            *(float2*)(C + (long long)row0 * D_ + col) = u0;
            *(float2*)(C + (long long)(row0 + 8) * D_ + col) = u1;
        }
    }
}

// ---------------- fused flash attention ------------------------------------
#define VST 68
#define PST 132

__device__ __forceinline__ float rmax16(float v) {
    v = fmaxf(v, __shfl_xor_sync(0xffffffffu, v, 8, 16));
    v = fmaxf(v, __shfl_xor_sync(0xffffffffu, v, 4, 16));
    v = fmaxf(v, __shfl_xor_sync(0xffffffffu, v, 2, 16));
    v = fmaxf(v, __shfl_xor_sync(0xffffffffu, v, 1, 16));
    return v;
}
__device__ __forceinline__ float rsum16(float v) {
    v += __shfl_xor_sync(0xffffffffu, v, 8, 16);
    v += __shfl_xor_sync(0xffffffffu, v, 4, 16);
    v += __shfl_xor_sync(0xffffffffu, v, 2, 16);
    v += __shfl_xor_sync(0xffffffffu, v, 1, 16);
    return v;
}

__global__ void __launch_bounds__(256) flash_kernel(const int* __restrict__ msk) {
    extern __shared__ float sm[];
    float* Qs = sm;                   // [64][128]
    float* Ks = sm + 8192;            // [64][128]
    float* Vs = sm + 16384;           // [128][VST]
    float* Ps = sm + 16384 + 128*VST; // [128][PST]

    int t = threadIdx.x;
    int ty4 = (t >> 4) << 2, tx4 = (t & 15) << 2;
    int i0 = blockIdx.x << 7;
    int h  = blockIdx.y;
    int b  = blockIdx.z;
    const float* Qg = g_q + (long long)b * N_ * D_ + h * DK_;
    const float* Kg = g_k + (long long)b * N_ * D_ + h * DK_;
    const float* Vg = g_v + (long long)b * N_ * D_ + h * DK_;
    const float* Fg = g_F + ((long long)(b * H_ + h)) * NN_ + (long long)i0 * N_;
    float* AOg = g_ao + (long long)b * N_ * D_ + h * DK_;
    const int* mrow = msk + b * N_;

    {
        int qi = t & 127;
        int qd0 = (t >> 7) << 2;
        const float* src = Qg + (long long)(i0 + qi) * D_;
        #pragma unroll
        for (int it = 0; it < 8; it++) {
            int d = qd0 + it * 8;
            float4 u = *(const float4*)(src + d);
            Qs[(d+0)*128 + qi] = u.x * 0.125f;
            Qs[(d+1)*128 + qi] = u.y * 0.125f;
            Qs[(d+2)*128 + qi] = u.z * 0.125f;
            Qs[(d+3)*128 + qi] = u.w * 0.125f;
        }
    }

    float O[8][4];
    float m8[8], l8[8];
    #pragma unroll
    for (int i = 0; i < 8; i++) {
        m8[i] = -1e30f; l8[i] = 0.0f;
        O[i][0] = O[i][1] = O[i][2] = O[i][3] = 0.0f;
    }
    int prow[8];
    #pragma unroll
    for (int ii = 0; ii < 8; ii++)
        prow[ii] = ((ii < 4) ? (ty4 + ii) : (64 + ty4 + ii - 4)) * PST;

    #pragma unroll 1
    for (int jt = 0; jt < 4; jt++) {
        int j0 = jt << 7;
        __syncthreads();
        {
            int kj = t & 127;
            int kd0 = (t >> 7) << 2;
            const float* src = Kg + (long long)(j0 + kj) * D_;
            #pragma unroll
            for (int it = 0; it < 8; it++) {
                int d = kd0 + it * 8;
                float4 u = *(const float4*)(src + d);
                Ks[(d+0)*128 + kj] = u.x;
                Ks[(d+1)*128 + kj] = u.y;
                Ks[(d+2)*128 + kj] = u.z;
                Ks[(d+3)*128 + kj] = u.w;
            }
        }
        {
            int vc = (t & 15) << 2;
            int vj = t >> 4;
            #pragma unroll
            for (int it = 0; it < 8; it++) {
                int j = vj + it * 16;
                *(float4*)&Vs[j * VST + vc] =
                    *(const float4*)(Vg + (long long)(j0 + j) * D_ + vc);
            }
        }
        __syncthreads();

        float S[8][8];
        #pragma unroll
        for (int i = 0; i < 8; i++)
            #pragma unroll
            for (int j = 0; j < 8; j++) S[i][j] = 0.0f;
        #pragma unroll 8
        for (int d = 0; d < 64; d++) {
            float4 q0 = *(const float4*)&Qs[d*128 + ty4];
            float4 q1 = *(const float4*)&Qs[d*128 + ty4 + 64];
            float4 k0 = *(const float4*)&Ks[d*128 + tx4];
            float4 k1 = *(const float4*)&Ks[d*128 + tx4 + 64];
            float qa[8] = {q0.x,q0.y,q0.z,q0.w,q1.x,q1.y,q1.z,q1.w};
            float kb[8] = {k0.x,k0.y,k0.z,k0.w,k1.x,k1.y,k1.z,k1.w};
            #pragma unroll
            for (int ii = 0; ii < 8; ii++)
                #pragma unroll
                for (int jj = 0; jj < 8; jj++)
                    S[ii][jj] = fmaf(qa[ii], kb[jj], S[ii][jj]);
        }

        int mc[8];
        #pragma unroll
        for (int jj = 0; jj < 8; jj++) {
            int cj = (jj < 4) ? (j0 + tx4 + jj) : (j0 + 64 + tx4 + jj - 4);
            mc[jj] = mrow[cj];
        }
        #pragma unroll
        for (int ii = 0; ii < 8; ii++)
            #pragma unroll
            for (int jj = 0; jj < 8; jj++)
                S[ii][jj] = mc[jj] ? S[ii][jj] : -1e9f;

        #pragma unroll
        for (int ii = 0; ii < 8; ii++) {
            float mx = S[ii][0];
            #pragma unroll
            for (int jj = 1; jj < 8; jj++) mx = fmaxf(mx, S[ii][jj]);
            mx = rmax16(mx);
            float mnew = fmaxf(m8[ii], mx);
            float fac = __expf(m8[ii] - mnew);
            m8[ii] = mnew;
            l8[ii] *= fac;
            O[ii][0] *= fac; O[ii][1] *= fac; O[ii][2] *= fac; O[ii][3] *= fac;
        }

        #pragma unroll
        for (int ii = 0; ii < 8; ii++) {
            int ig = (ii < 4) ? (ty4 + ii) : (64 + ty4 + ii - 4);
            const float* fr = Fg + (long long)ig * N_ + j0;
            float4 f0 = *(const float4*)(fr + tx4);
            float4 f1 = *(const float4*)(fr + 64 + tx4);
            float m = m8[ii];
            S[ii][0] = f0.x * __expf(S[ii][0] - m);
            S[ii][1] = f0.y * __expf(S[ii][1] - m);
            S[ii][2] = f0.z * __expf(S[ii][2] - m);
            S[ii][3] = f0.w * __expf(S[ii][3] - m);
            S[ii][4] = f1.x * __expf(S[ii][4] - m);
            S[ii][5] = f1.y * __expf(S[ii][5] - m);
            S[ii][6] = f1.z * __expf(S[ii][6] - m);
            S[ii][7] = f1.w * __expf(S[ii][7] - m);
            float rs = S[ii][0]+S[ii][1]+S[ii][2]+S[ii][3]
                     + S[ii][4]+S[ii][5]+S[ii][6]+S[ii][7];
            l8[ii] += rsum16(rs);
        }

        #pragma unroll
        for (int ii = 0; ii < 8; ii++) {
            *(float4*)&Ps[prow[ii] + tx4]      = make_float4(S[ii][0], S[ii][1], S[ii][2], S[ii][3]);
            *(float4*)&Ps[prow[ii] + 64 + tx4] = make_float4(S[ii][4], S[ii][5], S[ii][6], S[ii][7]);
        }
        __syncthreads();

        #pragma unroll 4
        for (int j = 0; j < 128; j += 4) {
            float4 v0 = *(const float4*)&Vs[(j+0)*VST + tx4];
            float4 v1 = *(const float4*)&Vs[(j+1)*VST + tx4];
            float4 v2 = *(const float4*)&Vs[(j+2)*VST + tx4];
            float4 v3 = *(const float4*)&Vs[(j+3)*VST + tx4];
            #pragma unroll
            for (int ii = 0; ii < 8; ii++) {
                float4 p = *(const float4*)&Ps[prow[ii] + j];
                O[ii][0] = fmaf(p.x, v0.x, O[ii][0]);
                O[ii][1] = fmaf(p.x, v0.y, O[ii][1]);
                O[ii][2] = fmaf(p.x, v0.z, O[ii][2]);
                O[ii][3] = fmaf(p.x, v0.w, O[ii][3]);
                O[ii][0] = fmaf(p.y, v1.x, O[ii][0]);
                O[ii][1] = fmaf(p.y, v1.y, O[ii][1]);
                O[ii][2] = fmaf(p.y, v1.z, O[ii][2]);
                O[ii][3] = fmaf(p.y, v1.w, O[ii][3]);
                O[ii][0] = fmaf(p.z, v2.x, O[ii][0]);
                O[ii][1] = fmaf(p.z, v2.y, O[ii][1]);
                O[ii][2] = fmaf(p.z, v2.z, O[ii][2]);
                O[ii][3] = fmaf(p.z, v2.w, O[ii][3]);
                O[ii][0] = fmaf(p.w, v3.x, O[ii][0]);
                O[ii][1] = fmaf(p.w, v3.y, O[ii][1]);
                O[ii][2] = fmaf(p.w, v3.z, O[ii][2]);
                O[ii][3] = fmaf(p.w, v3.w, O[ii][3]);
            }
        }
    }

    #pragma unroll
    for (int ii = 0; ii < 8; ii++) {
        int ig = i0 + ((ii < 4) ? (ty4 + ii) : (64 + ty4 + ii - 4));
        float inv = 1.0f / l8[ii];
        float4 o = make_float4(O[ii][0]*inv, O[ii][1]*inv, O[ii][2]*inv, O[ii][3]*inv);
        *(float4*)(AOg + (long long)ig * D_ + tx4) = o;
    }
}

#define FLASH_SMEM ((16384 + 128*VST + 128*PST) * 4)

// ---------------- launch ----------------------------------------------------
extern "C" void kernel_launch(void* const* d_in, const int* in_sizes, int n_in,
                              void* d_out, int out_size) {
    const float* inq = (const float*)d_in[0];
    const float* ink = (const float*)d_in[1];
    const float* inv = (const float*)d_in[2];
    const float* box = (const float*)d_in[3];
    const int*   msk = (const int*)d_in[4];
    const void*  nob = d_in[5];
    const float* Wq = (const float*)d_in[6];  const float* bq = (const float*)d_in[7];
    const float* Wk = (const float*)d_in[8];  const float* bk = (const float*)d_in[9];
    const float* Wv = (const float*)d_in[10]; const float* bv = (const float*)d_in[11];
    const float* Wo = (const float*)d_in[12]; const float* bo = (const float*)d_in[13];
    const float* WG = (const float*)d_in[14]; const float* bG = (const float*)d_in[15];
    float* out = (float*)d_out;

    float *pq, *pk, *pv, *pao;
    cudaGetSymbolAddress((void**)&pq,  g_q);
    cudaGetSymbolAddress((void**)&pk,  g_k);
    cudaGetSymbolAddress((void**)&pv,  g_v);
    cudaGetSymbolAddress((void**)&pao, g_ao);

    cudaFuncSetAttribute(flash_kernel, cudaFuncAttributeMaxDynamicSharedMemorySize, FLASH_SMEM);

    detect_nobj<<<1, 256>>>((const int*)nob);
    box_pre<<<32, 128>>>(box, nob);
    geom_kernel<<<BNT, 128>>>(WG, bG);

    // QKV projections in one launch: grid (8 n-tiles, 32 m-tiles, 3 problems)
    dim3 gQKV(8, 32, 3);
    proj_gemm<<<gQKV, 256>>>(inq, ink, inv,
                             Wq, Wk, Wv,
                             bq, bk, bv,
                             pq, pk, pv);

    flash_kernel<<<dim3(4, H_, B_), 256, FLASH_SMEM>>>(msk);

    // output projection
    dim3 gO(8, 32, 1);
    proj_gemm<<<gO, 256>>>(pao, pao, pao,
                           Wo, Wo, Wo,
                           bo, bo, bo,
                           out, out, out);
}

// round 6
// speedup vs baseline: 1.7605x; 1.4062x over previous
#include <cuda_runtime.h>
#include <math.h>
#include <stdint.h>

#define B_ 8
#define N_ 512
#define D_ 512
#define H_ 8
#define DK_ 64
#define BNT 4096                 // B*N
#define NN_ 262144               // N*N

// ---------------- scratch (static device globals; no allocation allowed) ----
__device__ float g_q [BNT * D_];
__device__ float g_k [BNT * D_];
__device__ float g_v [BNT * D_];
__device__ float g_ao[BNT * D_];
__device__ float g_F [(long long)B_ * H_ * NN_];   // geometry factor gfac
__device__ float g_cx[BNT], g_cy[BNT], g_iw[BNT], g_ih[BNT], g_no[BNT];
__device__ float g_tw[32][BNT];   // per-box sin/cos tables: [swW, cwW, swH, cwH] x 8 freqs
__device__ int   g_isbyte;

// 100 / 1000^(m/8)
__constant__ float c_DM[8] = {
    100.0f, 42.169650342858224f, 17.78279410038923f, 7.498942093324559f,
    3.1622776601683795f, 1.3335214321633242f, 0.5623413251903491f, 0.23713737056616555f};

// ---------------- detect layout of not_objects (bool-as-int32 vs bytes) ----
__global__ void detect_nobj(const int* __restrict__ p) {
    __shared__ int bad[256];
    int t = threadIdx.x;
    int v = 0;
    for (int i = t; i < 1024; i += 256) {
        int x = p[i];
        v |= (x != 0 && x != 1);
    }
    bad[t] = v;
    __syncthreads();
    for (int s = 128; s; s >>= 1) {
        if (t < s) bad[t] |= bad[t + s];
        __syncthreads();
    }
    if (t == 0) g_isbyte = bad[0];
}

// Cody-Waite reduced fast sincos: accurate for |x| up to ~800.
__device__ __forceinline__ void fsincos(float x, float& s, float& c) {
    float k = rintf(x * 0.15915494309189535f);
    float r = __fmaf_rn(k, -6.28125f, x);
    r = __fmaf_rn(k, -1.9353071795864769e-3f, r);
    s = __sinf(r);
    c = __cosf(r);
}

// ---------------- per-box precompute ---------------------------------------
__global__ void box_pre(const float* __restrict__ box, const void* __restrict__ nobj) {
    int i = blockIdx.x * blockDim.x + threadIdx.x;
    if (i >= BNT) return;
    float x0 = box[4*i+0], y0 = box[4*i+1], x1 = box[4*i+2], y1 = box[4*i+3];
    float w = x1 - x0 + 1.0f, h = y1 - y0 + 1.0f;
    g_cx[i] = 0.5f * (x0 + x1);
    g_cy[i] = 0.5f * (y0 + y1);
    g_iw[i] = 1.0f / w;
    g_ih[i] = 1.0f / h;
    float lw = logf(w), lh = logf(h);
    #pragma unroll
    for (int m = 0; m < 8; m++) {
        float s, c;
        fsincos(c_DM[m] * lw, s, c);
        g_tw[m][i] = s;      g_tw[8 + m][i] = c;
        fsincos(c_DM[m] * lh, s, c);
        g_tw[16 + m][i] = s; g_tw[24 + m][i] = c;
    }
    int nv = g_isbyte ? (int)((const unsigned char*)nobj)[i]
                      : ((const int*)nobj)[i];
    g_no[i] = nv ? 1.0f : 0.0f;
}

// ---------------- 3xTF32 helpers -------------------------------------------
__device__ __forceinline__ uint32_t cvt_tf32(float f) {
    uint32_t r;
    asm("cvt.rna.tf32.f32 %0, %1;" : "=r"(r) : "f"(f));
    return r;
}
__device__ __forceinline__ void split_tf32(float f, uint32_t& hi, uint32_t& lo) {
    hi = cvt_tf32(f);
    lo = cvt_tf32(f - __uint_as_float(hi));
}
__device__ __forceinline__ void mma_tf32(float* d, const uint32_t* a, const uint32_t* b) {
    asm("mma.sync.aligned.m16n8k8.row.col.f32.tf32.tf32.f32 "
        "{%0,%1,%2,%3}, {%4,%5,%6,%7}, {%8,%9}, {%0,%1,%2,%3};"
        : "+f"(d[0]), "+f"(d[1]), "+f"(d[2]), "+f"(d[3])
        : "r"(a[0]), "r"(a[1]), "r"(a[2]), "r"(a[3]), "r"(b[0]), "r"(b[1]));
}

// ---------------- geometry: gfac[b,h,i,j] via tensor-core reduction --------
// Block = one (b,i) row, 128 threads. Per 128-j slab: each thread builds its
// pair's 64-dim emb into smem (transposed), then 4 warps reduce 32 pairs each
// to 8 heads with 3xTF32 mma.
#define ETS 132
__global__ void __launch_bounds__(128) geom_kernel(const float* __restrict__ WG,
                                                   const float* __restrict__ bG) {
    __shared__ float embT[64][ETS];
    int t = threadIdx.x;
    int lane = t & 31, w = t >> 5;
    int frow = lane >> 2, fcol = lane & 3;
    int row = blockIdx.x;
    int b = row >> 9, i = row & 511;
    int base = b << 9;
    int gi = base + i;
    float cxi = g_cx[gi], cyi = g_cy[gi], iwi = g_iw[gi], ihi = g_ih[gi];
    float noi = g_no[gi];
    float swiW[8], cwiW[8], swiH[8], cwiH[8];
    #pragma unroll
    for (int m = 0; m < 8; m++) {
        swiW[m] = g_tw[m][gi];      cwiW[m] = g_tw[8 + m][gi];
        swiH[m] = g_tw[16 + m][gi]; cwiH[m] = g_tw[24 + m][gi];
    }
    // weight fragments: B(k=g, n=h) = WG[h*64+g], split hi/lo, per k-step
    uint32_t wbh[8][2], wbl[8][2];
    #pragma unroll
    for (int ks = 0; ks < 8; ks++) {
        split_tf32(WG[frow * 64 + ks * 8 + fcol],     wbh[ks][0], wbl[ks][0]);
        split_tf32(WG[frow * 64 + ks * 8 + fcol + 4], wbh[ks][1], wbl[ks][1]);
    }
    float bg0 = bG[2 * fcol], bg1 = bG[2 * fcol + 1];
    long long obase = (long long)b * H_ * NN_ + (long long)i * N_;

    for (int jt = 0; jt < 4; jt++) {
        int j0 = jt << 7;
        int jj = base + j0 + t;
        __syncthreads();   // protect embT reuse
        // ---- emb generation (this thread's pair) ----
        float dx = __logf(fmaxf(fabsf(g_cx[jj] - cxi) * iwi, 1e-3f));
        float dy = __logf(fmaxf(fabsf(g_cy[jj] - cyi) * ihi, 1e-3f));
        #pragma unroll
        for (int m = 0; m < 8; m++) {
            float s, c;
            fsincos(dx * c_DM[m], s, c);
            embT[m][t] = s;      embT[32 + m][t] = c;
            fsincos(dy * c_DM[m], s, c);
            embT[8 + m][t] = s;  embT[40 + m][t] = c;
            float swj = g_tw[m][jj], cwj = g_tw[8 + m][jj];
            embT[16 + m][t] = swiW[m] * cwj - cwiW[m] * swj;
            embT[48 + m][t] = cwiW[m] * cwj + swiW[m] * swj;
            float shj = g_tw[16 + m][jj], chj = g_tw[24 + m][jj];
            embT[24 + m][t] = swiH[m] * chj - cwiH[m] * shj;
            embT[56 + m][t] = cwiH[m] * chj + swiH[m] * shj;
        }
        __syncthreads();
        // ---- per-warp mma: 32 pairs -> 8 heads ----
        float acc[2][4];
        #pragma unroll
        for (int mt = 0; mt < 2; mt++)
            #pragma unroll
            for (int r = 0; r < 4; r++) acc[mt][r] = 0.0f;
        #pragma unroll
        for (int ks = 0; ks < 8; ks++) {
            #pragma unroll
            for (int mt = 0; mt < 2; mt++) {
                int p = (w << 5) + (mt << 4) + frow;
                float f0 = embT[ks * 8 + fcol][p];
                float f1 = embT[ks * 8 + fcol][p + 8];
                float f2 = embT[ks * 8 + fcol + 4][p];
                float f3 = embT[ks * 8 + fcol + 4][p + 8];
                uint32_t ah[4], al[4];
                split_tf32(f0, ah[0], al[0]);
                split_tf32(f1, ah[1], al[1]);
                split_tf32(f2, ah[2], al[2]);
                split_tf32(f3, ah[3], al[3]);
                mma_tf32(acc[mt], ah, wbh[ks]);
                mma_tf32(acc[mt], ah, wbl[ks]);
                mma_tf32(acc[mt], al, wbh[ks]);
            }
        }
        // ---- epilogue: bias, relu+clip, obj mask, store ----
        #pragma unroll
        for (int mt = 0; mt < 2; mt++) {
            int r0 = (w << 5) + (mt << 4) + frow;   // local j
            int r1 = r0 + 8;
            bool obj0 = (fmaxf(noi, g_no[base + j0 + r0]) < 0.5f);
            bool obj1 = (fmaxf(noi, g_no[base + j0 + r1]) < 0.5f);
            float v00 = acc[mt][0] + bg0, v01 = acc[mt][1] + bg1;
            float v10 = acc[mt][2] + bg0, v11 = acc[mt][3] + bg1;
            long long h0 = (long long)(2 * fcol) * NN_;
            long long h1 = h0 + NN_;
            g_F[obase + h0 + j0 + r0] = obj0 ? fmaxf(v00, 1e-6f) : 1.0f;
            g_F[obase + h1 + j0 + r0] = obj0 ? fmaxf(v01, 1e-6f) : 1.0f;
            g_F[obase + h0 + j0 + r1] = obj1 ? fmaxf(v10, 1e-6f) : 1.0f;
            g_F[obase + h1 + j0 + r1] = obj1 ? fmaxf(v11, 1e-6f) : 1.0f;
        }
    }
}

// ---------------- projection GEMM (3xTF32, pre-split smem) -----------------
// 128x64 block tile, 8 warps (4m x 2n), warp tile 32x32, double-buffered.
// hi/lo tf32 tiles built at load time -> mainloop is LDS + HMMA only.
#define AST 136
#define BST 72
#define A_SZ (16 * AST)
#define B_SZ (16 * BST)
#define PROJ_SMEM ((4 * A_SZ + 4 * B_SZ) * 4)
__global__ void __launch_bounds__(256, 2) proj_gemm(
    const float* __restrict__ A0, const float* __restrict__ A1, const float* __restrict__ A2,
    const float* __restrict__ W0, const float* __restrict__ W1, const float* __restrict__ W2,
    const float* __restrict__ b0p, const float* __restrict__ b1p, const float* __restrict__ b2p,
    float* __restrict__ C0, float* __restrict__ C1, float* __restrict__ C2)
{
    int z = blockIdx.z;
    const float* A = (z == 0) ? A0 : (z == 1) ? A1 : A2;
    const float* W = (z == 0) ? W0 : (z == 1) ? W1 : W2;
    const float* bias = (z == 0) ? b0p : (z == 1) ? b1p : b2p;
    float* C = (z == 0) ? C0 : (z == 1) ? C1 : C2;

    extern __shared__ uint32_t psm[];
    uint32_t* Ahi = psm;                    // [2][16][AST]
    uint32_t* Alo = psm + 2 * A_SZ;
    uint32_t* Bhi = psm + 4 * A_SZ;         // [2][16][BST]
    uint32_t* Blo = psm + 4 * A_SZ + 2 * B_SZ;

    int t = threadIdx.x;
    int lane = t & 31, wid = t >> 5;
    int wm = (wid & 3) << 5;
    int wn = (wid >> 2) << 5;
    int m0 = blockIdx.y << 7, n0 = blockIdx.x << 6;
    int am = t & 127, ak = (t >> 7) << 2;
    int bk = t >> 4,  bn = (t & 15) << 2;
    const float* Ap = A + (long long)(m0 + am) * D_;
    const float* Wp = W + n0;
    int frow = lane >> 2, fcol = lane & 3;

    float acc[2][4][4];
    #pragma unroll
    for (int i = 0; i < 2; i++)
        #pragma unroll
        for (int j = 0; j < 4; j++)
            #pragma unroll
            for (int r = 0; r < 4; r++) acc[i][j][r] = 0.0f;

    float4 a0 = *(const float4*)(Ap + ak);
    float4 a1 = *(const float4*)(Ap + ak + 8);
    float4 bb = *(const float4*)(Wp + (long long)bk * D_ + bn);

    #define STORE_TILES(BUF) do {                                              \
        uint32_t* ah_ = Ahi + (BUF) * A_SZ; uint32_t* al_ = Alo + (BUF) * A_SZ;\
        uint32_t* bh_ = Bhi + (BUF) * B_SZ; uint32_t* bl_ = Blo + (BUF) * B_SZ;\
        float av_[8] = {a0.x,a0.y,a0.z,a0.w,a1.x,a1.y,a1.z,a1.w};              \
        _Pragma("unroll")                                                      \
        for (int q_ = 0; q_ < 8; q_++) {                                       \
            int rr_ = (q_ < 4) ? (ak + q_) : (ak + 4 + q_);                    \
            uint32_t h_; split_tf32(av_[q_], h_, al_[rr_ * AST + am]);         \
            ah_[rr_ * AST + am] = h_;                                          \
        }                                                                      \
        float bv_[4] = {bb.x, bb.y, bb.z, bb.w};                               \
        _Pragma("unroll")                                                      \
        for (int q_ = 0; q_ < 4; q_++) {                                       \
            uint32_t h_; split_tf32(bv_[q_], h_, bl_[bk * BST + bn + q_]);     \
            bh_[bk * BST + bn + q_] = h_;                                      \
        }                                                                      \
    } while (0)

    STORE_TILES(0);
    __syncthreads();

    int buf = 0;
    for (int k0 = 0; k0 < D_; k0 += 16) {
        int kn = k0 + 16;
        if (kn < D_) {
            a0 = *(const float4*)(Ap + kn + ak);
            a1 = *(const float4*)(Ap + kn + ak + 8);
            bb = *(const float4*)(Wp + (long long)(kn + bk) * D_ + bn);
        }
        const uint32_t* ah_ = Ahi + buf * A_SZ;
        const uint32_t* al_ = Alo + buf * A_SZ;
        const uint32_t* bh_ = Bhi + buf * B_SZ;
        const uint32_t* bl_ = Blo + buf * B_SZ;
        #pragma unroll
        for (int ks = 0; ks < 16; ks += 8) {
            uint32_t afh[2][4], afl[2][4];
            #pragma unroll
            for (int mt = 0; mt < 2; mt++) {
                int mb = wm + (mt << 4) + frow;
                afh[mt][0] = ah_[(ks + fcol) * AST + mb];
                afh[mt][1] = ah_[(ks + fcol) * AST + mb + 8];
                afh[mt][2] = ah_[(ks + fcol + 4) * AST + mb];
                afh[mt][3] = ah_[(ks + fcol + 4) * AST + mb + 8];
                afl[mt][0] = al_[(ks + fcol) * AST + mb];
                afl[mt][1] = al_[(ks + fcol) * AST + mb + 8];
                afl[mt][2] = al_[(ks + fcol + 4) * AST + mb];
                afl[mt][3] = al_[(ks + fcol + 4) * AST + mb + 8];
            }
            uint32_t bfh[4][2], bfl[4][2];
            #pragma unroll
            for (int nt = 0; nt < 4; nt++) {
                int nb = wn + (nt << 3) + frow;
                bfh[nt][0] = bh_[(ks + fcol) * BST + nb];
                bfh[nt][1] = bh_[(ks + fcol + 4) * BST + nb];
                bfl[nt][0] = bl_[(ks + fcol) * BST + nb];
                bfl[nt][1] = bl_[(ks + fcol + 4) * BST + nb];
            }
            #pragma unroll
            for (int mt = 0; mt < 2; mt++)
                #pragma unroll
                for (int nt = 0; nt < 4; nt++) {
                    mma_tf32(acc[mt][nt], afh[mt], bfh[nt]);
                    mma_tf32(acc[mt][nt], afh[mt], bfl[nt]);
                    mma_tf32(acc[mt][nt], afl[mt], bfh[nt]);
                }
        }
        if (kn < D_) {
            buf ^= 1;
            STORE_TILES(buf);
        }
        __syncthreads();
    }

    #pragma unroll
    for (int mt = 0; mt < 2; mt++) {
        int row0 = m0 + wm + (mt << 4) + frow;
        #pragma unroll
        for (int nt = 0; nt < 4; nt++) {
            int col = n0 + wn + (nt << 3) + (fcol << 1);
            float bv0 = bias[col], bv1 = bias[col + 1];
            float2 u0 = make_float2(acc[mt][nt][0] + bv0, acc[mt][nt][1] + bv1);
            float2 u1 = make_float2(acc[mt][nt][2] + bv0, acc[mt][nt][3] + bv1);
            *(float2*)(C + (long long)row0 * D_ + col) = u0;
            *(float2*)(C + (long long)(row0 + 8) * D_ + col) = u1;
        }
    }
}

// ---------------- fused flash attention ------------------------------------
#define VST 68
#define PST 132

__device__ __forceinline__ float rmax16(float v) {
    v = fmaxf(v, __shfl_xor_sync(0xffffffffu, v, 8, 16));
    v = fmaxf(v, __shfl_xor_sync(0xffffffffu, v, 4, 16));
    v = fmaxf(v, __shfl_xor_sync(0xffffffffu, v, 2, 16));
    v = fmaxf(v, __shfl_xor_sync(0xffffffffu, v, 1, 16));
    return v;
}
__device__ __forceinline__ float rsum16(float v) {
    v += __shfl_xor_sync(0xffffffffu, v, 8, 16);
    v += __shfl_xor_sync(0xffffffffu, v, 4, 16);
    v += __shfl_xor_sync(0xffffffffu, v, 2, 16);
    v += __shfl_xor_sync(0xffffffffu, v, 1, 16);
    return v;
}

__global__ void __launch_bounds__(256) flash_kernel(const int* __restrict__ msk) {
    extern __shared__ float sm[];
    float* Qs = sm;                   // [64][128]
    float* Ks = sm + 8192;            // [64][128]
    float* Vs = sm + 16384;           // [128][VST]
    float* Ps = sm + 16384 + 128*VST; // [128][PST]

    int t = threadIdx.x;
    int ty4 = (t >> 4) << 2, tx4 = (t & 15) << 2;
    int i0 = blockIdx.x << 7;
    int h  = blockIdx.y;
    int b  = blockIdx.z;
    const float* Qg = g_q + (long long)b * N_ * D_ + h * DK_;
    const float* Kg = g_k + (long long)b * N_ * D_ + h * DK_;
    const float* Vg = g_v + (long long)b * N_ * D_ + h * DK_;
    const float* Fg = g_F + ((long long)(b * H_ + h)) * NN_ + (long long)i0 * N_;
    float* AOg = g_ao + (long long)b * N_ * D_ + h * DK_;
    const int* mrow = msk + b * N_;

    {
        int qi = t & 127;
        int qd0 = (t >> 7) << 2;
        const float* src = Qg + (long long)(i0 + qi) * D_;
        #pragma unroll
        for (int it = 0; it < 8; it++) {
            int d = qd0 + it * 8;
            float4 u = *(const float4*)(src + d);
            Qs[(d+0)*128 + qi] = u.x * 0.125f;
            Qs[(d+1)*128 + qi] = u.y * 0.125f;
            Qs[(d+2)*128 + qi] = u.z * 0.125f;
            Qs[(d+3)*128 + qi] = u.w * 0.125f;
        }
    }

    float O[8][4];
    float m8[8], l8[8];
    #pragma unroll
    for (int i = 0; i < 8; i++) {
        m8[i] = -1e30f; l8[i] = 0.0f;
        O[i][0] = O[i][1] = O[i][2] = O[i][3] = 0.0f;
    }
    int prow[8];
    #pragma unroll
    for (int ii = 0; ii < 8; ii++)
        prow[ii] = ((ii < 4) ? (ty4 + ii) : (64 + ty4 + ii - 4)) * PST;

    #pragma unroll 1
    for (int jt = 0; jt < 4; jt++) {
        int j0 = jt << 7;
        __syncthreads();
        {
            int kj = t & 127;
            int kd0 = (t >> 7) << 2;
            const float* src = Kg + (long long)(j0 + kj) * D_;
            #pragma unroll
            for (int it = 0; it < 8; it++) {
                int d = kd0 + it * 8;
                float4 u = *(const float4*)(src + d);
                Ks[(d+0)*128 + kj] = u.x;
                Ks[(d+1)*128 + kj] = u.y;
                Ks[(d+2)*128 + kj] = u.z;
                Ks[(d+3)*128 + kj] = u.w;
            }
        }
        {
            int vc = (t & 15) << 2;
            int vj = t >> 4;
            #pragma unroll
            for (int it = 0; it < 8; it++) {
                int j = vj + it * 16;
                *(float4*)&Vs[j * VST + vc] =
                    *(const float4*)(Vg + (long long)(j0 + j) * D_ + vc);
            }
        }
        __syncthreads();

        float S[8][8];
        #pragma unroll
        for (int i = 0; i < 8; i++)
            #pragma unroll
            for (int j = 0; j < 8; j++) S[i][j] = 0.0f;
        #pragma unroll 8
        for (int d = 0; d < 64; d++) {
            float4 q0 = *(const float4*)&Qs[d*128 + ty4];
            float4 q1 = *(const float4*)&Qs[d*128 + ty4 + 64];
            float4 k0 = *(const float4*)&Ks[d*128 + tx4];
            float4 k1 = *(const float4*)&Ks[d*128 + tx4 + 64];
            float qa[8] = {q0.x,q0.y,q0.z,q0.w,q1.x,q1.y,q1.z,q1.w};
            float kb[8] = {k0.x,k0.y,k0.z,k0.w,k1.x,k1.y,k1.z,k1.w};
            #pragma unroll
            for (int ii = 0; ii < 8; ii++)
                #pragma unroll
                for (int jj = 0; jj < 8; jj++)
                    S[ii][jj] = fmaf(qa[ii], kb[jj], S[ii][jj]);
        }

        int mc[8];
        #pragma unroll
        for (int jj = 0; jj < 8; jj++) {
            int cj = (jj < 4) ? (j0 + tx4 + jj) : (j0 + 64 + tx4 + jj - 4);
            mc[jj] = mrow[cj];
        }
        #pragma unroll
        for (int ii = 0; ii < 8; ii++)
            #pragma unroll
            for (int jj = 0; jj < 8; jj++)
                S[ii][jj] = mc[jj] ? S[ii][jj] : -1e9f;

        #pragma unroll
        for (int ii = 0; ii < 8; ii++) {
            float mx = S[ii][0];
            #pragma unroll
            for (int jj = 1; jj < 8; jj++) mx = fmaxf(mx, S[ii][jj]);
            mx = rmax16(mx);
            float mnew = fmaxf(m8[ii], mx);
            float fac = __expf(m8[ii] - mnew);
            m8[ii] = mnew;
            l8[ii] *= fac;
            O[ii][0] *= fac; O[ii][1] *= fac; O[ii][2] *= fac; O[ii][3] *= fac;
        }

        #pragma unroll
        for (int ii = 0; ii < 8; ii++) {
            int ig = (ii < 4) ? (ty4 + ii) : (64 + ty4 + ii - 4);
            const float* fr = Fg + (long long)ig * N_ + j0;
            float4 f0 = *(const float4*)(fr + tx4);
            float4 f1 = *(const float4*)(fr + 64 + tx4);
            float m = m8[ii];
            S[ii][0] = f0.x * __expf(S[ii][0] - m);
            S[ii][1] = f0.y * __expf(S[ii][1] - m);
            S[ii][2] = f0.z * __expf(S[ii][2] - m);
            S[ii][3] = f0.w * __expf(S[ii][3] - m);
            S[ii][4] = f1.x * __expf(S[ii][4] - m);
            S[ii][5] = f1.y * __expf(S[ii][5] - m);
            S[ii][6] = f1.z * __expf(S[ii][6] - m);
            S[ii][7] = f1.w * __expf(S[ii][7] - m);
            float rs = S[ii][0]+S[ii][1]+S[ii][2]+S[ii][3]
                     + S[ii][4]+S[ii][5]+S[ii][6]+S[ii][7];
            l8[ii] += rsum16(rs);
        }

        #pragma unroll
        for (int ii = 0; ii < 8; ii++) {
            *(float4*)&Ps[prow[ii] + tx4]      = make_float4(S[ii][0], S[ii][1], S[ii][2], S[ii][3]);
            *(float4*)&Ps[prow[ii] + 64 + tx4] = make_float4(S[ii][4], S[ii][5], S[ii][6], S[ii][7]);
        }
        __syncthreads();

        #pragma unroll 4
        for (int j = 0; j < 128; j += 4) {
            float4 v0 = *(const float4*)&Vs[(j+0)*VST + tx4];
            float4 v1 = *(const float4*)&Vs[(j+1)*VST + tx4];
            float4 v2 = *(const float4*)&Vs[(j+2)*VST + tx4];
            float4 v3 = *(const float4*)&Vs[(j+3)*VST + tx4];
            #pragma unroll
            for (int ii = 0; ii < 8; ii++) {
                float4 p = *(const float4*)&Ps[prow[ii] + j];
                O[ii][0] = fmaf(p.x, v0.x, O[ii][0]);
                O[ii][1] = fmaf(p.x, v0.y, O[ii][1]);
                O[ii][2] = fmaf(p.x, v0.z, O[ii][2]);
                O[ii][3] = fmaf(p.x, v0.w, O[ii][3]);
                O[ii][0] = fmaf(p.y, v1.x, O[ii][0]);
                O[ii][1] = fmaf(p.y, v1.y, O[ii][1]);
                O[ii][2] = fmaf(p.y, v1.z, O[ii][2]);
                O[ii][3] = fmaf(p.y, v1.w, O[ii][3]);
                O[ii][0] = fmaf(p.z, v2.x, O[ii][0]);
                O[ii][1] = fmaf(p.z, v2.y, O[ii][1]);
                O[ii][2] = fmaf(p.z, v2.z, O[ii][2]);
                O[ii][3] = fmaf(p.z, v2.w, O[ii][3]);
                O[ii][0] = fmaf(p.w, v3.x, O[ii][0]);
                O[ii][1] = fmaf(p.w, v3.y, O[ii][1]);
                O[ii][2] = fmaf(p.w, v3.z, O[ii][2]);
                O[ii][3] = fmaf(p.w, v3.w, O[ii][3]);
            }
        }
    }

    #pragma unroll
    for (int ii = 0; ii < 8; ii++) {
        int ig = i0 + ((ii < 4) ? (ty4 + ii) : (64 + ty4 + ii - 4));
        float inv = 1.0f / l8[ii];
        float4 o = make_float4(O[ii][0]*inv, O[ii][1]*inv, O[ii][2]*inv, O[ii][3]*inv);
        *(float4*)(AOg + (long long)ig * D_ + tx4) = o;
    }
}

#define FLASH_SMEM ((16384 + 128*VST + 128*PST) * 4)

// ---------------- launch ----------------------------------------------------
extern "C" void kernel_launch(void* const* d_in, const int* in_sizes, int n_in,
                              void* d_out, int out_size) {
    const float* inq = (const float*)d_in[0];
    const float* ink = (const float*)d_in[1];
    const float* inv = (const float*)d_in[2];
    const float* box = (const float*)d_in[3];
    const int*   msk = (const int*)d_in[4];
    const void*  nob = d_in[5];
    const float* Wq = (const float*)d_in[6];  const float* bq = (const float*)d_in[7];
    const float* Wk = (const float*)d_in[8];  const float* bk = (const float*)d_in[9];
    const float* Wv = (const float*)d_in[10]; const float* bv = (const float*)d_in[11];
    const float* Wo = (const float*)d_in[12]; const float* bo = (const float*)d_in[13];
    const float* WG = (const float*)d_in[14]; const float* bG = (const float*)d_in[15];
    float* out = (float*)d_out;

    float *pq, *pk, *pv, *pao;
    cudaGetSymbolAddress((void**)&pq,  g_q);
    cudaGetSymbolAddress((void**)&pk,  g_k);
    cudaGetSymbolAddress((void**)&pv,  g_v);
    cudaGetSymbolAddress((void**)&pao, g_ao);

    cudaFuncSetAttribute(flash_kernel, cudaFuncAttributeMaxDynamicSharedMemorySize, FLASH_SMEM);
    cudaFuncSetAttribute(proj_gemm, cudaFuncAttributeMaxDynamicSharedMemorySize, PROJ_SMEM);

    detect_nobj<<<1, 256>>>((const int*)nob);
    box_pre<<<32, 128>>>(box, nob);
    geom_kernel<<<BNT, 128>>>(WG, bG);

    // QKV projections in one launch: grid (8 n-tiles, 32 m-tiles, 3 problems)
    dim3 gQKV(8, 32, 3);
    proj_gemm<<<gQKV, 256, PROJ_SMEM>>>(inq, ink, inv,
                                        Wq, Wk, Wv,
                                        bq, bk, bv,
                                        pq, pk, pv);

    flash_kernel<<<dim3(4, H_, B_), 256, FLASH_SMEM>>>(msk);

    // output projection
    dim3 gO(8, 32, 1);
    proj_gemm<<<gO, 256, PROJ_SMEM>>>(pao, pao, pao,
                                      Wo, Wo, Wo,
                                      bo, bo, bo,
                                      out, out, out);
}

// round 7
// speedup vs baseline: 2.2753x; 1.2925x over previous
#include <cuda_runtime.h>
#include <math.h>
#include <stdint.h>

#define B_ 8
#define N_ 512
#define D_ 512
#define H_ 8
#define DK_ 64
#define BNT 4096                 // B*N
#define NN_ 262144               // N*N

// ---------------- scratch (static device globals; no allocation allowed) ----
__device__ float g_q [BNT * D_];
__device__ float g_k [BNT * D_];
__device__ float g_v [BNT * D_];
__device__ float g_ao[BNT * D_];
__device__ float g_F [(long long)B_ * H_ * NN_];   // geometry factor gfac
__device__ float g_cx[BNT], g_cy[BNT], g_iw[BNT], g_ih[BNT], g_no[BNT];
__device__ float g_tw[32][BNT];   // per-box sin/cos tables
__device__ int   g_isbyte;

// 100 / 1000^(m/8)
__constant__ float c_DM[8] = {
    100.0f, 42.169650342858224f, 17.78279410038923f, 7.498942093324559f,
    3.1622776601683795f, 1.3335214321633242f, 0.5623413251903491f, 0.23713737056616555f};

// ---------------- detect layout of not_objects (bool-as-int32 vs bytes) ----
__global__ void detect_nobj(const int* __restrict__ p) {
    __shared__ int bad[256];
    int t = threadIdx.x;
    int v = 0;
    for (int i = t; i < 1024; i += 256) {
        int x = p[i];
        v |= (x != 0 && x != 1);
    }
    bad[t] = v;
    __syncthreads();
    for (int s = 128; s; s >>= 1) {
        if (t < s) bad[t] |= bad[t + s];
        __syncthreads();
    }
    if (t == 0) g_isbyte = bad[0];
}

// Cody-Waite reduced fast sincos
__device__ __forceinline__ void fsincos(float x, float& s, float& c) {
    float k = rintf(x * 0.15915494309189535f);
    float r = __fmaf_rn(k, -6.28125f, x);
    r = __fmaf_rn(k, -1.9353071795864769e-3f, r);
    s = __sinf(r);
    c = __cosf(r);
}

// ---------------- per-box precompute ---------------------------------------
__global__ void box_pre(const float* __restrict__ box, const void* __restrict__ nobj) {
    int i = blockIdx.x * blockDim.x + threadIdx.x;
    if (i >= BNT) return;
    float x0 = box[4*i+0], y0 = box[4*i+1], x1 = box[4*i+2], y1 = box[4*i+3];
    float w = x1 - x0 + 1.0f, h = y1 - y0 + 1.0f;
    g_cx[i] = 0.5f * (x0 + x1);
    g_cy[i] = 0.5f * (y0 + y1);
    g_iw[i] = 1.0f / w;
    g_ih[i] = 1.0f / h;
    float lw = logf(w), lh = logf(h);
    #pragma unroll
    for (int m = 0; m < 8; m++) {
        float s, c;
        fsincos(c_DM[m] * lw, s, c);
        g_tw[m][i] = s;      g_tw[8 + m][i] = c;
        fsincos(c_DM[m] * lh, s, c);
        g_tw[16 + m][i] = s; g_tw[24 + m][i] = c;
    }
    int nv = g_isbyte ? (int)((const unsigned char*)nobj)[i]
                      : ((const int*)nobj)[i];
    g_no[i] = nv ? 1.0f : 0.0f;
}

// ---------------- TF32 helpers (geometry kernel) ----------------------------
__device__ __forceinline__ uint32_t cvt_tf32(float f) {
    uint32_t r;
    asm("cvt.rna.tf32.f32 %0, %1;" : "=r"(r) : "f"(f));
    return r;
}
__device__ __forceinline__ void split_tf32(float f, uint32_t& hi, uint32_t& lo) {
    hi = cvt_tf32(f);
    lo = cvt_tf32(f - __uint_as_float(hi));
}
__device__ __forceinline__ void mma_tf32(float* d, const uint32_t* a, const uint32_t* b) {
    asm("mma.sync.aligned.m16n8k8.row.col.f32.tf32.tf32.f32 "
        "{%0,%1,%2,%3}, {%4,%5,%6,%7}, {%8,%9}, {%0,%1,%2,%3};"
        : "+f"(d[0]), "+f"(d[1]), "+f"(d[2]), "+f"(d[3])
        : "r"(a[0]), "r"(a[1]), "r"(a[2]), "r"(a[3]), "r"(b[0]), "r"(b[1]));
}

// ---------------- BF16 2-plane helpers --------------------------------------
// word packs (even-k in low 16, odd-k in high 16)
__device__ __forceinline__ uint32_t pack_bf(float e, float o) {
    uint32_t r;
    asm("cvt.rn.bf16x2.f32 %0, %1, %2;" : "=r"(r) : "f"(o), "f"(e));
    return r;
}
__device__ __forceinline__ uint32_t resid_bf(float e, float o, uint32_t hw) {
    float eh = __uint_as_float(hw << 16);
    float oh = __uint_as_float(hw & 0xffff0000u);
    return pack_bf(e - eh, o - oh);
}
__device__ __forceinline__ void mma_bf16(float* d, const uint32_t* a, const uint32_t* b) {
    asm("mma.sync.aligned.m16n8k16.row.col.f32.bf16.bf16.f32 "
        "{%0,%1,%2,%3}, {%4,%5,%6,%7}, {%8,%9}, {%0,%1,%2,%3};"
        : "+f"(d[0]), "+f"(d[1]), "+f"(d[2]), "+f"(d[3])
        : "r"(a[0]), "r"(a[1]), "r"(a[2]), "r"(a[3]), "r"(b[0]), "r"(b[1]));
}

// ---------------- geometry: gfac[b,h,i,j] via tensor-core reduction --------
#define ETS 132
__global__ void __launch_bounds__(128) geom_kernel(const float* __restrict__ WG,
                                                   const float* __restrict__ bG) {
    __shared__ float embT[64][ETS];
    int t = threadIdx.x;
    int lane = t & 31, w = t >> 5;
    int frow = lane >> 2, fcol = lane & 3;
    int row = blockIdx.x;
    int b = row >> 9, i = row & 511;
    int base = b << 9;
    int gi = base + i;
    float cxi = g_cx[gi], cyi = g_cy[gi], iwi = g_iw[gi], ihi = g_ih[gi];
    float noi = g_no[gi];
    float swiW[8], cwiW[8], swiH[8], cwiH[8];
    #pragma unroll
    for (int m = 0; m < 8; m++) {
        swiW[m] = g_tw[m][gi];      cwiW[m] = g_tw[8 + m][gi];
        swiH[m] = g_tw[16 + m][gi]; cwiH[m] = g_tw[24 + m][gi];
    }
    uint32_t wbh[8][2], wbl[8][2];
    #pragma unroll
    for (int ks = 0; ks < 8; ks++) {
        split_tf32(WG[frow * 64 + ks * 8 + fcol],     wbh[ks][0], wbl[ks][0]);
        split_tf32(WG[frow * 64 + ks * 8 + fcol + 4], wbh[ks][1], wbl[ks][1]);
    }
    float bg0 = bG[2 * fcol], bg1 = bG[2 * fcol + 1];
    long long obase = (long long)b * H_ * NN_ + (long long)i * N_;

    for (int jt = 0; jt < 4; jt++) {
        int j0 = jt << 7;
        int jj = base + j0 + t;
        __syncthreads();
        float dx = __logf(fmaxf(fabsf(g_cx[jj] - cxi) * iwi, 1e-3f));
        float dy = __logf(fmaxf(fabsf(g_cy[jj] - cyi) * ihi, 1e-3f));
        #pragma unroll
        for (int m = 0; m < 8; m++) {
            float s, c;
            fsincos(dx * c_DM[m], s, c);
            embT[m][t] = s;      embT[32 + m][t] = c;
            fsincos(dy * c_DM[m], s, c);
            embT[8 + m][t] = s;  embT[40 + m][t] = c;
            float swj = g_tw[m][jj], cwj = g_tw[8 + m][jj];
            embT[16 + m][t] = swiW[m] * cwj - cwiW[m] * swj;
            embT[48 + m][t] = cwiW[m] * cwj + swiW[m] * swj;
            float shj = g_tw[16 + m][jj], chj = g_tw[24 + m][jj];
            embT[24 + m][t] = swiH[m] * chj - cwiH[m] * shj;
            embT[56 + m][t] = cwiH[m] * chj + swiH[m] * shj;
        }
        __syncthreads();
        float acc[2][4];
        #pragma unroll
        for (int mt = 0; mt < 2; mt++)
            #pragma unroll
            for (int r = 0; r < 4; r++) acc[mt][r] = 0.0f;
        #pragma unroll
        for (int ks = 0; ks < 8; ks++) {
            #pragma unroll
            for (int mt = 0; mt < 2; mt++) {
                int p = (w << 5) + (mt << 4) + frow;
                float f0 = embT[ks * 8 + fcol][p];
                float f1 = embT[ks * 8 + fcol][p + 8];
                float f2 = embT[ks * 8 + fcol + 4][p];
                float f3 = embT[ks * 8 + fcol + 4][p + 8];
                uint32_t ah[4], al[4];
                split_tf32(f0, ah[0], al[0]);
                split_tf32(f1, ah[1], al[1]);
                split_tf32(f2, ah[2], al[2]);
                split_tf32(f3, ah[3], al[3]);
                mma_tf32(acc[mt], ah, wbh[ks]);
                mma_tf32(acc[mt], ah, wbl[ks]);
                mma_tf32(acc[mt], al, wbh[ks]);
            }
        }
        #pragma unroll
        for (int mt = 0; mt < 2; mt++) {
            int r0 = (w << 5) + (mt << 4) + frow;
            int r1 = r0 + 8;
            bool obj0 = (fmaxf(noi, g_no[base + j0 + r0]) < 0.5f);
            bool obj1 = (fmaxf(noi, g_no[base + j0 + r1]) < 0.5f);
            float v00 = acc[mt][0] + bg0, v01 = acc[mt][1] + bg1;
            float v10 = acc[mt][2] + bg0, v11 = acc[mt][3] + bg1;
            long long h0 = (long long)(2 * fcol) * NN_;
            long long h1 = h0 + NN_;
            g_F[obase + h0 + j0 + r0] = obj0 ? fmaxf(v00, 1e-6f) : 1.0f;
            g_F[obase + h1 + j0 + r0] = obj0 ? fmaxf(v01, 1e-6f) : 1.0f;
            g_F[obase + h0 + j0 + r1] = obj1 ? fmaxf(v10, 1e-6f) : 1.0f;
            g_F[obase + h1 + j0 + r1] = obj1 ? fmaxf(v11, 1e-6f) : 1.0f;
        }
    }
}

// ---------------- projection GEMM (bf16 2-plane tensor core) ---------------
// 128x64 block tile, 8 warps (4m x 2n), warp tile 32x32, double-buffered.
// Planes store bf16x2 words k-major: [kword][row/col], k-pair packed per word.
#define PAS 136   // A plane stride (rows 128 + 8) -> bank = 8*fcol + frow
#define PBS 72    // B plane stride (cols 64 + 8)
#define PA_SZ (8 * PAS)
#define PB_SZ (8 * PBS)
__global__ void __launch_bounds__(256, 2) proj_gemm(
    const float* __restrict__ A0, const float* __restrict__ A1, const float* __restrict__ A2,
    const float* __restrict__ W0, const float* __restrict__ W1, const float* __restrict__ W2,
    const float* __restrict__ b0p, const float* __restrict__ b1p, const float* __restrict__ b2p,
    float* __restrict__ C0, float* __restrict__ C1, float* __restrict__ C2)
{
    int z = blockIdx.z;
    const float* A = (z == 0) ? A0 : (z == 1) ? A1 : A2;
    const float* W = (z == 0) ? W0 : (z == 1) ? W1 : W2;
    const float* bias = (z == 0) ? b0p : (z == 1) ? b1p : b2p;
    float* C = (z == 0) ? C0 : (z == 1) ? C1 : C2;

    __shared__ uint32_t AH[2][PA_SZ], AL[2][PA_SZ];
    __shared__ uint32_t BH[2][PB_SZ], BL[2][PB_SZ];

    int t = threadIdx.x;
    int lane = t & 31, wid = t >> 5;
    int wm = (wid & 3) << 5;
    int wn = (wid >> 2) << 5;
    int m0 = blockIdx.y << 7, n0 = blockIdx.x << 6;
    int frow = lane >> 2, fcol = lane & 3;

    // loader mapping
    int am = t & 127, ak = (t >> 7) << 2;          // A: row am, k ak..ak+3 & ak+8..
    int kp = t >> 5;                               // B: k-pair kp (0..7)
    int n2 = (lane) << 1;                          // B: cols n2, n2+1

    const float* Ap = A + (long long)(m0 + am) * D_;
    const float* Wp = W + n0;

    float acc[2][4][4];
    #pragma unroll
    for (int i = 0; i < 2; i++)
        #pragma unroll
        for (int j = 0; j < 4; j++)
            #pragma unroll
            for (int r = 0; r < 4; r++) acc[i][j][r] = 0.0f;

    float4 a0 = *(const float4*)(Ap + ak);
    float4 a1 = *(const float4*)(Ap + ak + 8);
    float2 w0 = *(const float2*)(Wp + (long long)(2 * kp) * D_ + n2);
    float2 w1 = *(const float2*)(Wp + (long long)(2 * kp + 1) * D_ + n2);

    #define PSTORE(BUF) do {                                                   \
        int kw0_ = ak >> 1;                                                    \
        uint32_t h_;                                                           \
        h_ = pack_bf(a0.x, a0.y); AH[BUF][(kw0_+0)*PAS + am] = h_;             \
        AL[BUF][(kw0_+0)*PAS + am] = resid_bf(a0.x, a0.y, h_);                 \
        h_ = pack_bf(a0.z, a0.w); AH[BUF][(kw0_+1)*PAS + am] = h_;             \
        AL[BUF][(kw0_+1)*PAS + am] = resid_bf(a0.z, a0.w, h_);                 \
        h_ = pack_bf(a1.x, a1.y); AH[BUF][(kw0_+4)*PAS + am] = h_;             \
        AL[BUF][(kw0_+4)*PAS + am] = resid_bf(a1.x, a1.y, h_);                 \
        h_ = pack_bf(a1.z, a1.w); AH[BUF][(kw0_+5)*PAS + am] = h_;             \
        AL[BUF][(kw0_+5)*PAS + am] = resid_bf(a1.z, a1.w, h_);                 \
        h_ = pack_bf(w0.x, w1.x); BH[BUF][kp*PBS + n2] = h_;                   \
        BL[BUF][kp*PBS + n2] = resid_bf(w0.x, w1.x, h_);                       \
        h_ = pack_bf(w0.y, w1.y); BH[BUF][kp*PBS + n2 + 1] = h_;               \
        BL[BUF][kp*PBS + n2 + 1] = resid_bf(w0.y, w1.y, h_);                   \
    } while (0)

    PSTORE(0);
    __syncthreads();

    int buf = 0;
    for (int k0 = 0; k0 < D_; k0 += 16) {
        int kn = k0 + 16;
        if (kn < D_) {
            a0 = *(const float4*)(Ap + kn + ak);
            a1 = *(const float4*)(Ap + kn + ak + 8);
            w0 = *(const float2*)(Wp + (long long)(kn + 2 * kp) * D_ + n2);
            w1 = *(const float2*)(Wp + (long long)(kn + 2 * kp + 1) * D_ + n2);
        }
        // one k16 step
        {
            uint32_t ah[2][4], al[2][4];
            #pragma unroll
            for (int mt = 0; mt < 2; mt++) {
                int mb = wm + (mt << 4) + frow;
                ah[mt][0] = AH[buf][fcol * PAS + mb];
                ah[mt][1] = AH[buf][fcol * PAS + mb + 8];
                ah[mt][2] = AH[buf][(fcol + 4) * PAS + mb];
                ah[mt][3] = AH[buf][(fcol + 4) * PAS + mb + 8];
                al[mt][0] = AL[buf][fcol * PAS + mb];
                al[mt][1] = AL[buf][fcol * PAS + mb + 8];
                al[mt][2] = AL[buf][(fcol + 4) * PAS + mb];
                al[mt][3] = AL[buf][(fcol + 4) * PAS + mb + 8];
            }
            uint32_t bh[4][2], bl[4][2];
            #pragma unroll
            for (int nt = 0; nt < 4; nt++) {
                int nb = wn + (nt << 3) + frow;
                bh[nt][0] = BH[buf][fcol * PBS + nb];
                bh[nt][1] = BH[buf][(fcol + 4) * PBS + nb];
                bl[nt][0] = BL[buf][fcol * PBS + nb];
                bl[nt][1] = BL[buf][(fcol + 4) * PBS + nb];
            }
            #pragma unroll
            for (int mt = 0; mt < 2; mt++)
                #pragma unroll
                for (int nt = 0; nt < 4; nt++) {
                    mma_bf16(acc[mt][nt], ah[mt], bh[nt]);
                    mma_bf16(acc[mt][nt], ah[mt], bl[nt]);
                    mma_bf16(acc[mt][nt], al[mt], bh[nt]);
                }
        }
        if (kn < D_) {
            buf ^= 1;
            PSTORE(buf);
        }
        __syncthreads();
    }

    #pragma unroll
    for (int mt = 0; mt < 2; mt++) {
        int row0 = m0 + wm + (mt << 4) + frow;
        #pragma unroll
        for (int nt = 0; nt < 4; nt++) {
            int col = n0 + wn + (nt << 3) + (fcol << 1);
            float bv0 = bias[col], bv1 = bias[col + 1];
            float2 u0 = make_float2(acc[mt][nt][0] + bv0, acc[mt][nt][1] + bv1);
            float2 u1 = make_float2(acc[mt][nt][2] + bv0, acc[mt][nt][3] + bv1);
            *(float2*)(C + (long long)row0 * D_ + col) = u0;
            *(float2*)(C + (long long)(row0 + 8) * D_ + col) = u1;
        }
    }
}

// ---------------- fused flash attention (bf16 2-plane tensor core) ---------
// Block: 128 q-rows x one (b,h); 8 warps: QK grid 4m x 2n (32x64 warp tile),
// PV grid 4m x 2n over d (32x32). Online softmax in fragment layout with one
// cross-warp smem exchange per j-tile. All smem planes bank-conflict-free.
#define FQH 0
#define FQL 4352
#define FKH 8704
#define FKL 13056
#define FVH 17408
#define FVL 22016
#define FPH 26624
#define FPL 35328
#define FRM 44032
#define FRS 44288
#define FLASH_SMEM (44544 * 4)
#define QKS 136   // Q/K plane stride
#define VSP 72    // V plane stride
#define PSP 136   // P plane stride

__global__ void __launch_bounds__(256) flash_kernel(const int* __restrict__ msk) {
    extern __shared__ uint32_t fsm[];
    float* redm = (float*)(fsm + FRM);
    float* reds = (float*)(fsm + FRS);

    int t = threadIdx.x;
    int lane = t & 31, w = t >> 5;
    int wm = (w & 3) << 5;        // 0,32,64,96
    int wn = w >> 2;              // 0,1
    int frow = lane >> 2, fcol = lane & 3;
    int i0 = blockIdx.x << 7;
    int h  = blockIdx.y;
    int b  = blockIdx.z;
    const float* Qg = g_q + (long long)b * N_ * D_ + h * DK_;
    const float* Kg = g_k + (long long)b * N_ * D_ + h * DK_;
    const float* Vg = g_v + (long long)b * N_ * D_ + h * DK_;
    const float* Fg = g_F + ((long long)(b * H_ + h)) * NN_ + (long long)i0 * N_;
    float* AOg = g_ao + (long long)b * N_ * D_ + h * DK_;
    const int* mrow = msk + b * N_;

    // ---- load Q planes (pre-scaled 0.125), [kword d][row i] ----
    {
        int qi = t & 127, half = t >> 7;
        const float* src = Qg + (long long)(i0 + qi) * D_;
        #pragma unroll
        for (int it = 0; it < 8; it++) {
            int d0 = half * 32 + it * 4;
            float4 u = *(const float4*)(src + d0);
            u.x *= 0.125f; u.y *= 0.125f; u.z *= 0.125f; u.w *= 0.125f;
            int kw = d0 >> 1;
            uint32_t h0 = pack_bf(u.x, u.y);
            uint32_t h1 = pack_bf(u.z, u.w);
            fsm[FQH + (kw + 0) * QKS + qi] = h0;
            fsm[FQL + (kw + 0) * QKS + qi] = resid_bf(u.x, u.y, h0);
            fsm[FQH + (kw + 1) * QKS + qi] = h1;
            fsm[FQL + (kw + 1) * QKS + qi] = resid_bf(u.z, u.w, h1);
        }
    }

    float O[2][4][4];
    float m8[2][2], l8[2][2];
    #pragma unroll
    for (int mt = 0; mt < 2; mt++) {
        m8[mt][0] = -1e30f; m8[mt][1] = -1e30f;
        l8[mt][0] = 0.0f;   l8[mt][1] = 0.0f;
        #pragma unroll
        for (int nt = 0; nt < 4; nt++)
            #pragma unroll
            for (int r = 0; r < 4; r++) O[mt][nt][r] = 0.0f;
    }

    #pragma unroll 1
    for (int jt = 0; jt < 4; jt++) {
        int j0 = jt << 7;
        __syncthreads();   // prev PV done; Q ready on jt=0
        // ---- K planes: [kword d][row j] ----
        {
            int kj = t & 127, half = t >> 7;
            const float* src = Kg + (long long)(j0 + kj) * D_;
            #pragma unroll
            for (int it = 0; it < 8; it++) {
                int d0 = half * 32 + it * 4;
                float4 u = *(const float4*)(src + d0);
                int kw = d0 >> 1;
                uint32_t h0 = pack_bf(u.x, u.y);
                uint32_t h1 = pack_bf(u.z, u.w);
                fsm[FKH + (kw + 0) * QKS + kj] = h0;
                fsm[FKL + (kw + 0) * QKS + kj] = resid_bf(u.x, u.y, h0);
                fsm[FKH + (kw + 1) * QKS + kj] = h1;
                fsm[FKL + (kw + 1) * QKS + kj] = resid_bf(u.z, u.w, h1);
            }
        }
        // ---- V planes: [kword j][col d], pairs along j ----
        {
            int d4 = (t & 15) << 2;
            int jp0 = t >> 4;
            #pragma unroll
            for (int it = 0; it < 4; it++) {
                int jp = jp0 + it * 16;
                const float* v0p = Vg + (long long)(j0 + 2 * jp) * D_ + d4;
                float4 x = *(const float4*)v0p;
                float4 y = *(const float4*)(v0p + D_);
                uint32_t hw;
                hw = pack_bf(x.x, y.x);
                fsm[FVH + jp * VSP + d4 + 0] = hw;
                fsm[FVL + jp * VSP + d4 + 0] = resid_bf(x.x, y.x, hw);
                hw = pack_bf(x.y, y.y);
                fsm[FVH + jp * VSP + d4 + 1] = hw;
                fsm[FVL + jp * VSP + d4 + 1] = resid_bf(x.y, y.y, hw);
                hw = pack_bf(x.z, y.z);
                fsm[FVH + jp * VSP + d4 + 2] = hw;
                fsm[FVL + jp * VSP + d4 + 2] = resid_bf(x.z, y.z, hw);
                hw = pack_bf(x.w, y.w);
                fsm[FVH + jp * VSP + d4 + 3] = hw;
                fsm[FVL + jp * VSP + d4 + 3] = resid_bf(x.w, y.w, hw);
            }
        }
        __syncthreads();

        // ---- S = Q @ K^T : 4 k16 steps over d=64 ----
        float S[2][8][4];
        #pragma unroll
        for (int mt = 0; mt < 2; mt++)
            #pragma unroll
            for (int nt = 0; nt < 8; nt++)
                #pragma unroll
                for (int r = 0; r < 4; r++) S[mt][nt][r] = 0.0f;
        #pragma unroll
        for (int ks = 0; ks < 4; ks++) {
            uint32_t ah[2][4], al[2][4];
            #pragma unroll
            for (int mt = 0; mt < 2; mt++) {
                int mb = wm + (mt << 4) + frow;
                int r0 = (ks * 8 + fcol) * QKS, r1 = (ks * 8 + fcol + 4) * QKS;
                ah[mt][0] = fsm[FQH + r0 + mb]; ah[mt][1] = fsm[FQH + r0 + mb + 8];
                ah[mt][2] = fsm[FQH + r1 + mb]; ah[mt][3] = fsm[FQH + r1 + mb + 8];
                al[mt][0] = fsm[FQL + r0 + mb]; al[mt][1] = fsm[FQL + r0 + mb + 8];
                al[mt][2] = fsm[FQL + r1 + mb]; al[mt][3] = fsm[FQL + r1 + mb + 8];
            }
            #pragma unroll
            for (int nt = 0; nt < 8; nt++) {
                int nb = wn * 64 + (nt << 3) + frow;
                int r0 = (ks * 8 + fcol) * QKS, r1 = (ks * 8 + fcol + 4) * QKS;
                uint32_t bh[2], bl[2];
                bh[0] = fsm[FKH + r0 + nb]; bh[1] = fsm[FKH + r1 + nb];
                bl[0] = fsm[FKL + r0 + nb]; bl[1] = fsm[FKL + r1 + nb];
                #pragma unroll
                for (int mt = 0; mt < 2; mt++) {
                    mma_bf16(S[mt][nt], ah[mt], bh);
                    mma_bf16(S[mt][nt], ah[mt], bl);
                    mma_bf16(S[mt][nt], al[mt], bh);
                }
            }
        }

        // ---- mask ----
        #pragma unroll
        for (int nt = 0; nt < 8; nt++) {
            int c = j0 + wn * 64 + (nt << 3) + (fcol << 1);
            int q0 = mrow[c], q1 = mrow[c + 1];
            if (!q0) { S[0][nt][0] = -1e9f; S[0][nt][2] = -1e9f;
                       S[1][nt][0] = -1e9f; S[1][nt][2] = -1e9f; }
            if (!q1) { S[0][nt][1] = -1e9f; S[0][nt][3] = -1e9f;
                       S[1][nt][1] = -1e9f; S[1][nt][3] = -1e9f; }
        }

        // ---- row max (local -> quad -> cross-warp) ----
        float mx[2][2];
        #pragma unroll
        for (int mt = 0; mt < 2; mt++) {
            float a = -1e30f, c2 = -1e30f;
            #pragma unroll
            for (int nt = 0; nt < 8; nt++) {
                a  = fmaxf(a,  fmaxf(S[mt][nt][0], S[mt][nt][1]));
                c2 = fmaxf(c2, fmaxf(S[mt][nt][2], S[mt][nt][3]));
            }
            a  = fmaxf(a,  __shfl_xor_sync(0xffffffffu, a, 1));
            a  = fmaxf(a,  __shfl_xor_sync(0xffffffffu, a, 2));
            c2 = fmaxf(c2, __shfl_xor_sync(0xffffffffu, c2, 1));
            c2 = fmaxf(c2, __shfl_xor_sync(0xffffffffu, c2, 2));
            mx[mt][0] = a; mx[mt][1] = c2;
        }
        if (fcol == 0) {
            #pragma unroll
            for (int mt = 0; mt < 2; mt++) {
                int rl = wm + (mt << 4) + frow;
                redm[wn * 128 + rl] = mx[mt][0];
                redm[wn * 128 + rl + 8] = mx[mt][1];
            }
        }
        __syncthreads();
        float mnew[2][2], fac[2][2];
        #pragma unroll
        for (int mt = 0; mt < 2; mt++) {
            int rl = wm + (mt << 4) + frow;
            float f0 = fmaxf(mx[mt][0], redm[(1 ^ wn) * 128 + rl]);
            float f1 = fmaxf(mx[mt][1], redm[(1 ^ wn) * 128 + rl + 8]);
            mnew[mt][0] = fmaxf(m8[mt][0], f0);
            mnew[mt][1] = fmaxf(m8[mt][1], f1);
            fac[mt][0] = __expf(m8[mt][0] - mnew[mt][0]);
            fac[mt][1] = __expf(m8[mt][1] - mnew[mt][1]);
            m8[mt][0] = mnew[mt][0]; m8[mt][1] = mnew[mt][1];
            l8[mt][0] *= fac[mt][0]; l8[mt][1] *= fac[mt][1];
            #pragma unroll
            for (int nt = 0; nt < 4; nt++) {
                O[mt][nt][0] *= fac[mt][0]; O[mt][nt][1] *= fac[mt][0];
                O[mt][nt][2] *= fac[mt][1]; O[mt][nt][3] *= fac[mt][1];
            }
        }

        // ---- p = F * exp(s - m); sums; pack P planes ----
        float sm2[2][2] = {{0.0f, 0.0f}, {0.0f, 0.0f}};
        #pragma unroll
        for (int mt = 0; mt < 2; mt++) {
            int rl = wm + (mt << 4) + frow;
            #pragma unroll
            for (int nt = 0; nt < 8; nt++) {
                const float* fp = Fg + (long long)rl * N_ + j0 + wn * 64 + (nt << 3) + (fcol << 1);
                float2 f0 = *(const float2*)fp;
                float2 f1 = *(const float2*)(fp + 8 * N_);
                float p0 = f0.x * __expf(S[mt][nt][0] - mnew[mt][0]);
                float p1 = f0.y * __expf(S[mt][nt][1] - mnew[mt][0]);
                float p2 = f1.x * __expf(S[mt][nt][2] - mnew[mt][1]);
                float p3 = f1.y * __expf(S[mt][nt][3] - mnew[mt][1]);
                sm2[mt][0] += p0 + p1;
                sm2[mt][1] += p2 + p3;
                int kw = wn * 32 + (nt << 2) + fcol;
                uint32_t h0 = pack_bf(p0, p1);
                fsm[FPH + kw * PSP + rl] = h0;
                fsm[FPL + kw * PSP + rl] = resid_bf(p0, p1, h0);
                uint32_t h1 = pack_bf(p2, p3);
                fsm[FPH + kw * PSP + rl + 8] = h1;
                fsm[FPL + kw * PSP + rl + 8] = resid_bf(p2, p3, h1);
            }
        }
        #pragma unroll
        for (int mt = 0; mt < 2; mt++) {
            sm2[mt][0] += __shfl_xor_sync(0xffffffffu, sm2[mt][0], 1);
            sm2[mt][0] += __shfl_xor_sync(0xffffffffu, sm2[mt][0], 2);
            sm2[mt][1] += __shfl_xor_sync(0xffffffffu, sm2[mt][1], 1);
            sm2[mt][1] += __shfl_xor_sync(0xffffffffu, sm2[mt][1], 2);
        }
        if (fcol == 0) {
            #pragma unroll
            for (int mt = 0; mt < 2; mt++) {
                int rl = wm + (mt << 4) + frow;
                reds[wn * 128 + rl] = sm2[mt][0];
                reds[wn * 128 + rl + 8] = sm2[mt][1];
            }
        }
        __syncthreads();   // covers P-plane visibility + reds
        #pragma unroll
        for (int mt = 0; mt < 2; mt++) {
            int rl = wm + (mt << 4) + frow;
            l8[mt][0] += sm2[mt][0] + reds[(1 ^ wn) * 128 + rl];
            l8[mt][1] += sm2[mt][1] + reds[(1 ^ wn) * 128 + rl + 8];
        }

        // ---- O += P @ V : 8 k16 steps over j=128, d-cols wn*32+nt*8 ----
        #pragma unroll
        for (int ks = 0; ks < 8; ks++) {
            uint32_t ah[2][4], al[2][4];
            #pragma unroll
            for (int mt = 0; mt < 2; mt++) {
                int mb = wm + (mt << 4) + frow;
                int r0 = (ks * 8 + fcol) * PSP, r1 = (ks * 8 + fcol + 4) * PSP;
                ah[mt][0] = fsm[FPH + r0 + mb]; ah[mt][1] = fsm[FPH + r0 + mb + 8];
                ah[mt][2] = fsm[FPH + r1 + mb]; ah[mt][3] = fsm[FPH + r1 + mb + 8];
                al[mt][0] = fsm[FPL + r0 + mb]; al[mt][1] = fsm[FPL + r0 + mb + 8];
                al[mt][2] = fsm[FPL + r1 + mb]; al[mt][3] = fsm[FPL + r1 + mb + 8];
            }
            #pragma unroll
            for (int nt = 0; nt < 4; nt++) {
                int nb = wn * 32 + (nt << 3) + frow;
                int r0 = (ks * 8 + fcol) * VSP, r1 = (ks * 8 + fcol + 4) * VSP;
                uint32_t bh[2], bl[2];
                bh[0] = fsm[FVH + r0 + nb]; bh[1] = fsm[FVH + r1 + nb];
                bl[0] = fsm[FVL + r0 + nb]; bl[1] = fsm[FVL + r1 + nb];
                #pragma unroll
                for (int mt = 0; mt < 2; mt++) {
                    mma_bf16(O[mt][nt], ah[mt], bh);
                    mma_bf16(O[mt][nt], al[mt], bh);
                    mma_bf16(O[mt][nt], ah[mt], bl);
                }
            }
        }
    }

    // ---- epilogue ----
    #pragma unroll
    for (int mt = 0; mt < 2; mt++) {
        float inv0 = 1.0f / l8[mt][0];
        float inv1 = 1.0f / l8[mt][1];
        int row = i0 + wm + (mt << 4) + frow;
        #pragma unroll
        for (int nt = 0; nt < 4; nt++) {
            int col = wn * 32 + (nt << 3) + (fcol << 1);
            float2 u0 = make_float2(O[mt][nt][0] * inv0, O[mt][nt][1] * inv0);
            float2 u1 = make_float2(O[mt][nt][2] * inv1, O[mt][nt][3] * inv1);
            *(float2*)(AOg + (long long)row * D_ + col) = u0;
            *(float2*)(AOg + (long long)(row + 8) * D_ + col) = u1;
        }
    }
}

// ---------------- launch ----------------------------------------------------
extern "C" void kernel_launch(void* const* d_in, const int* in_sizes, int n_in,
                              void* d_out, int out_size) {
    const float* inq = (const float*)d_in[0];
    const float* ink = (const float*)d_in[1];
    const float* inv = (const float*)d_in[2];
    const float* box = (const float*)d_in[3];
    const int*   msk = (const int*)d_in[4];
    const void*  nob = d_in[5];
    const float* Wq = (const float*)d_in[6];  const float* bq = (const float*)d_in[7];
    const float* Wk = (const float*)d_in[8];  const float* bk = (const float*)d_in[9];
    const float* Wv = (const float*)d_in[10]; const float* bv = (const float*)d_in[11];
    const float* Wo = (const float*)d_in[12]; const float* bo = (const float*)d_in[13];
    const float* WG = (const float*)d_in[14]; const float* bG = (const float*)d_in[15];
    float* out = (float*)d_out;

    float *pq, *pk, *pv, *pao;
    cudaGetSymbolAddress((void**)&pq,  g_q);
    cudaGetSymbolAddress((void**)&pk,  g_k);
    cudaGetSymbolAddress((void**)&pv,  g_v);
    cudaGetSymbolAddress((void**)&pao, g_ao);

    cudaFuncSetAttribute(flash_kernel, cudaFuncAttributeMaxDynamicSharedMemorySize, FLASH_SMEM);

    detect_nobj<<<1, 256>>>((const int*)nob);
    box_pre<<<32, 128>>>(box, nob);
    geom_kernel<<<BNT, 128>>>(WG, bG);

    dim3 gQKV(8, 32, 3);
    proj_gemm<<<gQKV, 256>>>(inq, ink, inv,
                             Wq, Wk, Wv,
                             bq, bk, bv,
                             pq, pk, pv);

    flash_kernel<<<dim3(4, H_, B_), 256, FLASH_SMEM>>>(msk);

    dim3 gO(8, 32, 1);
    proj_gemm<<<gO, 256>>>(pao, pao, pao,
                           Wo, Wo, Wo,
                           bo, bo, bo,
                           out, out, out);
}